// round 13
// baseline (speedup 1.0000x reference)
#include <cuda_runtime.h>
#include <math.h>
#include <stdint.h>

#define B_SZ   4
#define SEQ    4096
#define DMODEL 512
#define DIN    1024
#define NH     16
#define HD     64
#define DS     64
#define NCH    16
#define CHUNK  256
#define CONVDIM 1152
#define DPROJ  2192
#define NTOK   (B_SZ*SEQ)   // 16384

// ---------------- scratch (device globals; no runtime alloc) ----------------
__device__ float g_zx[(size_t)NTOK*DPROJ];
__device__ float g_xbc[(size_t)NTOK*CONVDIM];
__device__ float g_dt[NTOK*NH];
__device__ float g_acum[B_SZ*NCH*NH*CHUNK];
__device__ float g_states[B_SZ*NCH*NH*HD*DS];
__device__ float g_prefix[B_SZ*NCH*NH*HD*DS];
__device__ float g_y[(size_t)NTOK*DIN];
__device__ uint2 g_act_hi[(size_t)NTOK*DIN/4];
__device__ uint2 g_act_lo[(size_t)NTOK*DIN/4];
__device__ uint2 g_w_hi[(DPROJ*DMODEL)/4];
__device__ uint2 g_w_lo[(DPROJ*DMODEL)/4];

// ---------------- tf32 helpers (SSD kernels) ----------------
__device__ __forceinline__ uint32_t cvt_tf32(float f) {
    uint32_t r; asm("cvt.rna.tf32.f32 %0, %1;" : "=r"(r) : "f"(f)); return r;
}
__device__ __forceinline__ float tf32r(float f) { return __uint_as_float(cvt_tf32(f)); }

__device__ __forceinline__ void mma8(float* c, const float* a, const float* b) {
    asm volatile("mma.sync.aligned.m16n8k8.row.col.f32.tf32.tf32.f32 "
        "{%0,%1,%2,%3}, {%4,%5,%6,%7}, {%8,%9}, {%0,%1,%2,%3};"
        : "+f"(c[0]), "+f"(c[1]), "+f"(c[2]), "+f"(c[3])
        : "r"(__float_as_uint(a[0])), "r"(__float_as_uint(a[1])),
          "r"(__float_as_uint(a[2])), "r"(__float_as_uint(a[3])),
          "r"(__float_as_uint(b[0])), "r"(__float_as_uint(b[1])));
}
__device__ __forceinline__ void mma_bf16(float* c, const uint32_t* a, const uint32_t* b) {
    asm volatile("mma.sync.aligned.m16n8k16.row.col.f32.bf16.bf16.f32 "
        "{%0,%1,%2,%3}, {%4,%5,%6,%7}, {%8,%9}, {%0,%1,%2,%3};"
        : "+f"(c[0]), "+f"(c[1]), "+f"(c[2]), "+f"(c[3])
        : "r"(a[0]), "r"(a[1]), "r"(a[2]), "r"(a[3]), "r"(b[0]), "r"(b[1]));
}

__device__ __forceinline__ void bsplit2(float2 p, uint32_t& hi, uint32_t& lo) {
    uint32_t ux = __float_as_uint(p.x), uy = __float_as_uint(p.y);
    hi = __byte_perm(ux, uy, 0x7632);
    float rx = p.x - __uint_as_float(ux & 0xffff0000u);
    float ry = p.y - __uint_as_float(uy & 0xffff0000u);
    lo = __byte_perm(__float_as_uint(rx), __float_as_uint(ry), 0x7632);
}

__device__ __forceinline__ int sw64(int r, int c) {
    return r * 64 + ((((c >> 2) ^ (r & 7)) << 2) | (c & 3));
}
__device__ __forceinline__ uint32_t smem_u32(const void* p) {
    uint32_t a;
    asm("{ .reg .u64 t; cvta.to.shared.u64 t, %1; cvt.u32.u64 %0, t; }" : "=r"(a) : "l"(p));
    return a;
}
#define LDSM4(r0,r1,r2,r3,addr) \
    asm volatile("ldmatrix.sync.aligned.m8n8.x4.shared.b16 {%0,%1,%2,%3}, [%4];" \
        : "=r"(r0), "=r"(r1), "=r"(r2), "=r"(r3) : "r"(addr))

// ---------------- fp32 -> bf16 hi/lo split ----------------
__global__ __launch_bounds__(256) void split_kernel(const float4* __restrict__ src,
                                                    uint2* __restrict__ hi,
                                                    uint2* __restrict__ lo, int n4) {
    int i = blockIdx.x * 256 + threadIdx.x;
    if (i >= n4) return;
    float4 v = src[i];
    uint32_t h0, l0, h1, l1;
    bsplit2(make_float2(v.x, v.y), h0, l0);
    bsplit2(make_float2(v.z, v.w), h1, l1);
    hi[i] = make_uint2(h0, h1);
    lo[i] = make_uint2(l0, l1);
}

// ======= bf16 GEMM, pre-split inputs: C = A @ B^T (hi*hi + hi*lo + lo*hi) =======
// tile 128x128, BK=16, 3-stage cp.async, 256 threads (8 warps, warp tile m32 x n64).
// stage layout (bytes): Ahi[128x32B]=4K @0, Alo @4K, Bhi @8K, Blo @12K; stride 16K; 3 stages = 48KB.
// 32B rows; 16B chunk c of row r at r*32 + (((c ^ (r>>2)) & 1)<<4).
__global__ __launch_bounds__(256) void gemm_bf16ld(const uint16_t* __restrict__ Ahi,
                                                   const uint16_t* __restrict__ Alo,
                                                   const uint16_t* __restrict__ Bhi,
                                                   const uint16_t* __restrict__ Blo,
                                                   float* __restrict__ C,
                                                   int M, int N, int K) {
    __shared__ char smem[49152];
    uint32_t sb0 = smem_u32(smem);
    int tid = threadIdx.x, lane = tid & 31, wid = tid >> 5;
    int wm = wid >> 1, wn = wid & 1;
    int g = lane >> 2, tg = lane & 3;
    int rowBase = blockIdx.y * 128, colBase = blockIdx.x * 128;

    // ldmatrix per-lane addressing within a 16-row group
    int lrow = lane & 15;
    int lch = lane >> 4;

    float acc[2][8][4];
#pragma unroll
    for (int i = 0; i < 2; i++)
#pragma unroll
        for (int j = 0; j < 8; j++)
#pragma unroll
            for (int q = 0; q < 4; q++) acc[i][j][q] = 0.f;

    int KT = K >> 4;
    auto loadTile = [&](int buf, int k0) {
        uint32_t base = sb0 + buf * 16384;
        // A: 256 chunks (128 rows x 2 chunks of 8 bf16); 1 hi + 1 lo per thread
        {
            int r = tid >> 1, c = tid & 1;
            uint32_t off = (uint32_t)(r * 32 + (((c ^ (r >> 2)) & 1) << 4));
            const uint16_t* sh = &Ahi[(size_t)(rowBase + r) * K + k0 + c * 8];
            const uint16_t* sl = &Alo[(size_t)(rowBase + r) * K + k0 + c * 8];
            asm volatile("cp.async.ca.shared.global [%0], [%1], 16;" :: "r"(base + off), "l"(sh));
            asm volatile("cp.async.ca.shared.global [%0], [%1], 16;" :: "r"(base + 4096 + off), "l"(sl));
        }
        // B: 256 chunks, predicated
        {
            int r = tid >> 1, c = tid & 1;
            int nrow = colBase + r;
            uint32_t off = (uint32_t)(r * 32 + (((c ^ (r >> 2)) & 1) << 4));
            const uint16_t* sh = &Bhi[(size_t)(nrow < N ? nrow : 0) * K + k0 + c * 8];
            const uint16_t* sl = &Blo[(size_t)(nrow < N ? nrow : 0) * K + k0 + c * 8];
            int sz = (nrow < N) ? 16 : 0;
            asm volatile("cp.async.ca.shared.global [%0], [%1], 16, %2;" :: "r"(base + 8192 + off), "l"(sh), "r"(sz));
            asm volatile("cp.async.ca.shared.global [%0], [%1], 16, %2;" :: "r"(base + 12288 + off), "l"(sl), "r"(sz));
        }
        asm volatile("cp.async.commit_group;");
    };

    loadTile(0, 0);
    if (KT > 1) loadTile(1, 16);
    for (int kt = 0; kt < KT; kt++) {
        if (kt + 2 < KT) {
            loadTile((kt + 2) % 3, (kt + 2) * 16);
            asm volatile("cp.async.wait_group 2;");
        } else if (kt + 1 < KT) {
            asm volatile("cp.async.wait_group 1;");
        } else {
            asm volatile("cp.async.wait_group 0;");
        }
        __syncthreads();
        uint32_t base = sb0 + (kt % 3) * 16384;

        // A fragments: 2 m16 tiles, hi+lo
        uint32_t ah[2][4], al[2][4];
#pragma unroll
        for (int tm = 0; tm < 2; tm++) {
            int rr = wm * 32 + tm * 16 + lrow;
            uint32_t off = (uint32_t)(rr * 32 + (((lch ^ (rr >> 2)) & 1) << 4));
            LDSM4(ah[tm][0], ah[tm][1], ah[tm][2], ah[tm][3], base + off);
            LDSM4(al[tm][0], al[tm][1], al[tm][2], al[tm][3], base + 4096 + off);
        }
        // B fragments: 4 n16 groups, hi+lo
        uint32_t bh[4][4], bl[4][4];
#pragma unroll
        for (int p = 0; p < 4; p++) {
            int rr = wn * 64 + p * 16 + lrow;
            uint32_t off = (uint32_t)(rr * 32 + (((lch ^ (rr >> 2)) & 1) << 4));
            LDSM4(bh[p][0], bh[p][1], bh[p][2], bh[p][3], base + 8192 + off);
            LDSM4(bl[p][0], bl[p][1], bl[p][2], bl[p][3], base + 12288 + off);
        }
#pragma unroll
        for (int tm = 0; tm < 2; tm++)
#pragma unroll
            for (int tn = 0; tn < 8; tn++) {
                int p = tn >> 1, sub = tn & 1;
                uint32_t bfh[2] = { bh[p][sub], bh[p][sub + 2] };
                uint32_t bfl[2] = { bl[p][sub], bl[p][sub + 2] };
                mma_bf16(acc[tm][tn], ah[tm], bfh);
                mma_bf16(acc[tm][tn], ah[tm], bfl);
                mma_bf16(acc[tm][tn], al[tm], bfh);
            }
        __syncthreads();
    }
#pragma unroll
    for (int tm = 0; tm < 2; tm++) {
        int r0 = rowBase + wm * 32 + tm * 16;
#pragma unroll
        for (int tn = 0; tn < 8; tn++) {
            int c0 = colBase + wn * 64 + tn * 8 + tg * 2;
            if (c0 < N) {
                *(float2*)&C[(size_t)(r0 + g) * N + c0]     = make_float2(acc[tm][tn][0], acc[tm][tn][1]);
                *(float2*)&C[(size_t)(r0 + g + 8) * N + c0] = make_float2(acc[tm][tn][2], acc[tm][tn][3]);
            }
        }
    }
}

// ---------------- causal conv1d (width 4) + SiLU, sliding-window ----------------
__global__ __launch_bounds__(256) void conv_kernel(const float* __restrict__ zx,
                                                   const float* __restrict__ conv_w,
                                                   const float* __restrict__ conv_b,
                                                   float* __restrict__ xbc) {
    int idx = blockIdx.x * 256 + threadIdx.x;
    int c = idx % CONVDIM;
    int bl4 = idx / CONVDIM;
    int b = bl4 / (SEQ / 4);
    int l0 = (bl4 % (SEQ / 4)) * 4;

    float w0 = conv_w[c * 4 + 0], w1 = conv_w[c * 4 + 1];
    float w2 = conv_w[c * 4 + 2], w3 = conv_w[c * 4 + 3];
    float bias = conv_b[c];

    float v[7];
#pragma unroll
    for (int k = 0; k < 7; k++) {
        int ls = l0 - 3 + k;
        v[k] = (ls >= 0) ? zx[(size_t)(b * SEQ + ls) * DPROJ + DIN + c] : 0.f;
    }
#pragma unroll
    for (int j = 0; j < 4; j++) {
        float a = bias + v[j] * w0 + v[j + 1] * w1 + v[j + 2] * w2 + v[j + 3] * w3;
        xbc[(size_t)(b * SEQ + l0 + j) * CONVDIM + c] = a / (1.f + __expf(-a));
    }
}

// ---------------- dt softplus + per-chunk cumsum of dt*A ----------------
__global__ __launch_bounds__(256) void dt_acum_kernel(const float* __restrict__ zx,
                                                      const float* __restrict__ dt_bias,
                                                      const float* __restrict__ A_log,
                                                      float* __restrict__ dtp,
                                                      float* __restrict__ acum) {
    int bc = blockIdx.x;
    int h = blockIdx.y;
    int b = bc >> 4, c = bc & 15;
    int l = threadIdx.x;
    int row = b * SEQ + c * CHUNK + l;
    float x = zx[(size_t)row * DPROJ + (DPROJ - NH) + h] + dt_bias[h];
    float dtv = (x > 20.f) ? x : log1pf(expf(x));
    dtp[row * NH + h] = dtv;
    float a = -expf(A_log[h]) * dtv;

    __shared__ float s[CHUNK];
    s[l] = a;
    __syncthreads();
#pragma unroll
    for (int off = 1; off < CHUNK; off <<= 1) {
        float v = (l >= off) ? s[l - off] : 0.f;
        __syncthreads();
        s[l] += v;
        __syncthreads();
    }
    acum[(bc * NH + h) * CHUNK + l] = s[l];
}

// =================== MMA intra-chunk Y_diag, 64x64 tiles ===================
__global__ __launch_bounds__(128) void ydiag_mma(const float* __restrict__ xbc,
                                                 const float* __restrict__ dtp,
                                                 const float* __restrict__ acum,
                                                 float* __restrict__ y) {
    extern __shared__ float sm[];
    float* sB = sm;
    float* sX = sm + 4096;
    float* sS = sm + 8192;

    int bc = blockIdx.x, h = blockIdx.y, lt = blockIdx.z;
    int b = bc >> 4, c = bc & 15;
    int rowBase = b * SEQ + c * CHUNK;
    int tid = threadIdx.x, lane = tid & 31, w = tid >> 5;
    int g = lane >> 2, tg = lane & 3;
    int lbase = lt * 64;
    const float* acbase = &acum[(bc * NH + h) * CHUNK];

    float creg[8][4];
    {
        const float* c0 = &xbc[(size_t)(rowBase + lbase + w * 16 + g) * CONVDIM + DIN + DS];
        const float* c1 = &xbc[(size_t)(rowBase + lbase + w * 16 + g + 8) * CONVDIM + DIN + DS];
#pragma unroll
        for (int kb8 = 0; kb8 < 8; kb8++) {
            int kb = kb8 * 8;
            creg[kb8][0] = tf32r(c0[kb + tg]);
            creg[kb8][1] = tf32r(c1[kb + tg]);
            creg[kb8][2] = tf32r(c0[kb + tg + 4]);
            creg[kb8][3] = tf32r(c1[kb + tg + 4]);
        }
    }
    float aL0 = acbase[lbase + w * 16 + g];
    float aL1 = acbase[lbase + w * 16 + g + 8];
    int lg0 = lbase + w * 16 + g, lg1 = lg0 + 8;

    float accY[8][4];
#pragma unroll
    for (int nt = 0; nt < 8; nt++)
#pragma unroll
        for (int q = 0; q < 4; q++) accY[nt][q] = 0.f;

    for (int st = 0; st <= lt; st++) {
        __syncthreads();
        int sbase = st * 64;
        for (int i = tid; i < 64 * 16; i += 128) {
            int r = i >> 4, q = (i & 15) * 4;
            size_t grow = (size_t)(rowBase + sbase + r);
            float4 bv = *(const float4*)&xbc[grow * CONVDIM + DIN + q];
            float4 bt = make_float4(tf32r(bv.x), tf32r(bv.y), tf32r(bv.z), tf32r(bv.w));
            *(float4*)&sB[r * 64 + ((((q >> 2) ^ (r & 7)) << 2))] = bt;
            float dtv = dtp[grow * NH + h];
            float4 xv = *(const float4*)&xbc[grow * CONVDIM + h * HD + q];
            float4 xt = make_float4(tf32r(xv.x * dtv), tf32r(xv.y * dtv),
                                    tf32r(xv.z * dtv), tf32r(xv.w * dtv));
            *(float4*)&sX[r * 64 + ((((q >> 2) ^ (r & 7)) << 2))] = xt;
        }
        __syncthreads();

        float accS[8][4];
#pragma unroll
        for (int nt = 0; nt < 8; nt++)
#pragma unroll
            for (int q = 0; q < 4; q++) accS[nt][q] = 0.f;
#pragma unroll
        for (int kb8 = 0; kb8 < 8; kb8++) {
            int kb = kb8 * 8;
#pragma unroll
            for (int nt = 0; nt < 8; nt++) {
                float bf[2] = { sB[sw64(nt * 8 + g, kb + tg)],
                                sB[sw64(nt * 8 + g, kb + tg + 4)] };
                mma8(accS[nt], creg[kb8], bf);
            }
        }
#pragma unroll
        for (int nt = 0; nt < 8; nt++) {
            int col0 = nt * 8 + 2 * tg;
            int s0 = sbase + col0, s1 = s0 + 1;
            float as0 = __ldg(&acbase[s0]), as1 = __ldg(&acbase[s1]);
            float w00 = (s0 <= lg0) ? __expf(aL0 - as0) : 0.f;
            float w01 = (s1 <= lg0) ? __expf(aL0 - as1) : 0.f;
            float w10 = (s0 <= lg1) ? __expf(aL1 - as0) : 0.f;
            float w11 = (s1 <= lg1) ? __expf(aL1 - as1) : 0.f;
            *(float2*)&sS[sw64(w * 16 + g, col0)] =
                make_float2(tf32r(accS[nt][0] * w00), tf32r(accS[nt][1] * w01));
            *(float2*)&sS[sw64(w * 16 + g + 8, col0)] =
                make_float2(tf32r(accS[nt][2] * w10), tf32r(accS[nt][3] * w11));
        }
        __syncwarp();

#pragma unroll
        for (int kb8 = 0; kb8 < 8; kb8++) {
            int kb = kb8 * 8;
            float a[4];
            a[0] = sS[sw64(w * 16 + g, kb + tg)];
            a[1] = sS[sw64(w * 16 + g + 8, kb + tg)];
            a[2] = sS[sw64(w * 16 + g, kb + tg + 4)];
            a[3] = sS[sw64(w * 16 + g + 8, kb + tg + 4)];
#pragma unroll
            for (int nt = 0; nt < 8; nt++) {
                float bf[2] = { sX[sw64(kb + tg, nt * 8 + g)],
                                sX[sw64(kb + tg + 4, nt * 8 + g)] };
                mma8(accY[nt], a, bf);
            }
        }
    }
    size_t r0 = (size_t)(rowBase + lbase + w * 16 + g);
#pragma unroll
    for (int nt = 0; nt < 8; nt++) {
        int col = h * HD + nt * 8 + 2 * tg;
        *(float2*)&y[r0 * DIN + col]       = make_float2(accY[nt][0], accY[nt][1]);
        *(float2*)&y[(r0 + 8) * DIN + col] = make_float2(accY[nt][2], accY[nt][3]);
    }
}

// =================== MMA per-chunk states ===================
__global__ __launch_bounds__(128) void states_mma(const float* __restrict__ xbc,
                                                  const float* __restrict__ dtp,
                                                  const float* __restrict__ acum,
                                                  float* __restrict__ states) {
    __shared__ float sX[4096];
    __shared__ float sB[4096];

    int bc = blockIdx.x, h = blockIdx.y;
    int b = bc >> 4, c = bc & 15;
    int rowBase = b * SEQ + c * CHUNK;
    int tid = threadIdx.x, lane = tid & 31, w = tid >> 5;
    int g = lane >> 2, tg = lane & 3;
    int m0 = w * 16;
    const float* acbase = &acum[(bc * NH + h) * CHUNK];
    float aEnd = acbase[CHUNK - 1];

    float acc[8][4];
#pragma unroll
    for (int nt = 0; nt < 8; nt++)
#pragma unroll
        for (int q = 0; q < 4; q++) acc[nt][q] = 0.f;

    for (int st = 0; st < 4; st++) {
        __syncthreads();
        int sbase = st * 64;
        for (int i = tid; i < 64 * 16; i += 128) {
            int r = i >> 4, q = (i & 15) * 4;
            size_t grow = (size_t)(rowBase + sbase + r);
            float dec = __expf(aEnd - acbase[sbase + r]);
            float dtv = dtp[grow * NH + h] * dec;
            float4 xv = *(const float4*)&xbc[grow * CONVDIM + h * HD + q];
            float4 xt = make_float4(tf32r(xv.x * dtv), tf32r(xv.y * dtv),
                                    tf32r(xv.z * dtv), tf32r(xv.w * dtv));
            *(float4*)&sX[r * 64 + ((((q >> 2) ^ (r & 7)) << 2))] = xt;
            float4 bv = *(const float4*)&xbc[grow * CONVDIM + DIN + q];
            float4 bt = make_float4(tf32r(bv.x), tf32r(bv.y), tf32r(bv.z), tf32r(bv.w));
            *(float4*)&sB[r * 64 + ((((q >> 2) ^ (r & 7)) << 2))] = bt;
        }
        __syncthreads();
#pragma unroll
        for (int kb8 = 0; kb8 < 8; kb8++) {
            int kb = kb8 * 8;
            float a[4];
            a[0] = sX[sw64(kb + tg, m0 + g)];
            a[1] = sX[sw64(kb + tg, m0 + g + 8)];
            a[2] = sX[sw64(kb + tg + 4, m0 + g)];
            a[3] = sX[sw64(kb + tg + 4, m0 + g + 8)];
#pragma unroll
            for (int nt = 0; nt < 8; nt++) {
                float bf[2] = { sB[sw64(nt * 8 + g, kb + tg)],
                                sB[sw64(nt * 8 + g, kb + tg + 4)] };
                mma8(acc[nt], a, bf);
            }
        }
    }
    size_t base = (size_t)(bc * NH + h) * (HD * DS);
#pragma unroll
    for (int nt = 0; nt < 8; nt++) {
        int col = nt * 8 + 2 * tg;
        *(float2*)&states[base + (m0 + g) * DS + col]     = make_float2(acc[nt][0], acc[nt][1]);
        *(float2*)&states[base + (m0 + g + 8) * DS + col] = make_float2(acc[nt][2], acc[nt][3]);
    }
}

// ---------------- inter-chunk sequential scan ----------------
__global__ __launch_bounds__(256) void scan_kernel(const float* __restrict__ acum,
                                                   const float* __restrict__ states,
                                                   float* __restrict__ prefix) {
    int b = blockIdx.x, h = blockIdx.y, t = threadIdx.x;
    float S[16];
#pragma unroll
    for (int j = 0; j < 16; j++) S[j] = 0.f;
    for (int c = 0; c < NCH; c++) {
        size_t base = ((size_t)((b * NCH + c) * NH + h)) * (HD * DS) + t * 16;
#pragma unroll
        for (int j = 0; j < 16; j += 4) {
            float4 v = make_float4(S[j], S[j + 1], S[j + 2], S[j + 3]);
            *(float4*)&prefix[base + j] = v;
        }
        float cs = __expf(acum[((b * NCH + c) * NH + h) * CHUNK + (CHUNK - 1)]);
#pragma unroll
        for (int j = 0; j < 16; j += 4) {
            float4 sv = *(const float4*)&states[base + j];
            S[j + 0] = cs * S[j + 0] + sv.x;
            S[j + 1] = cs * S[j + 1] + sv.y;
            S[j + 2] = cs * S[j + 2] + sv.z;
            S[j + 3] = cs * S[j + 3] + sv.w;
        }
    }
}

// =================== MMA Y_off + D*xh ===================
__global__ __launch_bounds__(128) void yoff_mma(const float* __restrict__ xbc,
                                                const float* __restrict__ prefix,
                                                const float* __restrict__ acum,
                                                const float* __restrict__ Dv,
                                                float* __restrict__ y) {
    __shared__ float sP[4096];

    int bc = blockIdx.x, h = blockIdx.y, lt = blockIdx.z;
    int b = bc >> 4, c = bc & 15;
    int rowBase = b * SEQ + c * CHUNK;
    int tid = threadIdx.x, lane = tid & 31, w = tid >> 5;
    int g = lane >> 2, tg = lane & 3;
    int lbase = lt * 64;

    size_t pbase = (size_t)(bc * NH + h) * (HD * DS);
    for (int i = tid; i < 64 * 16; i += 128) {
        int r = i >> 4, q = (i & 15) * 4;
        float4 v = *(const float4*)&prefix[pbase + r * DS + q];
        float4 vt = make_float4(tf32r(v.x), tf32r(v.y), tf32r(v.z), tf32r(v.w));
        *(float4*)&sP[r * 64 + ((((q >> 2) ^ (r & 7)) << 2))] = vt;
    }

    float creg[8][4];
    {
        const float* c0 = &xbc[(size_t)(rowBase + lbase + w * 16 + g) * CONVDIM + DIN + DS];
        const float* c1 = &xbc[(size_t)(rowBase + lbase + w * 16 + g + 8) * CONVDIM + DIN + DS];
#pragma unroll
        for (int kb8 = 0; kb8 < 8; kb8++) {
            int kb = kb8 * 8;
            creg[kb8][0] = tf32r(c0[kb + tg]);
            creg[kb8][1] = tf32r(c1[kb + tg]);
            creg[kb8][2] = tf32r(c0[kb + tg + 4]);
            creg[kb8][3] = tf32r(c1[kb + tg + 4]);
        }
    }
    __syncthreads();

    float acc[8][4];
#pragma unroll
    for (int nt = 0; nt < 8; nt++)
#pragma unroll
        for (int q = 0; q < 4; q++) acc[nt][q] = 0.f;

#pragma unroll
    for (int kb8 = 0; kb8 < 8; kb8++) {
        int kb = kb8 * 8;
#pragma unroll
        for (int nt = 0; nt < 8; nt++) {
            float bf[2] = { sP[sw64(nt * 8 + g, kb + tg)],
                            sP[sw64(nt * 8 + g, kb + tg + 4)] };
            mma8(acc[nt], creg[kb8], bf);
        }
    }

    float Dh = Dv[h];
    float ae0 = __expf(acum[(bc * NH + h) * CHUNK + lbase + w * 16 + g]);
    float ae1 = __expf(acum[(bc * NH + h) * CHUNK + lbase + w * 16 + g + 8]);
    size_t grow = (size_t)(rowBase + lbase + w * 16 + g);
#pragma unroll
    for (int nt = 0; nt < 8; nt++) {
        int col = h * HD + nt * 8 + 2 * tg;
        float2 yv0 = *(float2*)&y[grow * DIN + col];
        float2 xh0 = *(const float2*)&xbc[grow * CONVDIM + col];
        float2 yv1 = *(float2*)&y[(grow + 8) * DIN + col];
        float2 xh1 = *(const float2*)&xbc[(grow + 8) * CONVDIM + col];
        yv0.x += ae0 * acc[nt][0] + Dh * xh0.x;
        yv0.y += ae0 * acc[nt][1] + Dh * xh0.y;
        yv1.x += ae1 * acc[nt][2] + Dh * xh1.x;
        yv1.y += ae1 * acc[nt][3] + Dh * xh1.y;
        *(float2*)&y[grow * DIN + col] = yv0;
        *(float2*)&y[(grow + 8) * DIN + col] = yv1;
    }
}

// ---------------- gate + RMSNorm, emitting bf16 hi/lo directly ----------------
__global__ __launch_bounds__(256) void gate_norm_kernel(const float* __restrict__ zx,
                                                        const float* __restrict__ norm_w,
                                                        const float* __restrict__ y,
                                                        uint2* __restrict__ out_hi,
                                                        uint2* __restrict__ out_lo) {
    int row = blockIdx.x;
    int t = threadIdx.x;
    float4 yv = ((const float4*)&y[(size_t)row * DIN])[t];
    float4 zv = ((const float4*)&zx[(size_t)row * DPROJ])[t];
    float g0 = yv.x * (zv.x / (1.f + __expf(-zv.x)));
    float g1 = yv.y * (zv.y / (1.f + __expf(-zv.y)));
    float g2 = yv.z * (zv.z / (1.f + __expf(-zv.z)));
    float g3 = yv.w * (zv.w / (1.f + __expf(-zv.w)));
    float ss = g0 * g0 + g1 * g1 + g2 * g2 + g3 * g3;
#pragma unroll
    for (int o = 16; o; o >>= 1) ss += __shfl_xor_sync(0xffffffffu, ss, o);
    __shared__ float red[8];
    if ((t & 31) == 0) red[t >> 5] = ss;
    __syncthreads();
    float tot = red[0] + red[1] + red[2] + red[3] + red[4] + red[5] + red[6] + red[7];
    float rms = rsqrtf(tot / (float)DIN + 1e-5f);
    float4 nw = ((const float4*)norm_w)[t];
    float o0 = g0 * rms * nw.x, o1 = g1 * rms * nw.y;
    float o2 = g2 * rms * nw.z, o3 = g3 * rms * nw.w;
    uint32_t h0, l0, h1, l1;
    bsplit2(make_float2(o0, o1), h0, l0);
    bsplit2(make_float2(o2, o3), h1, l1);
    out_hi[(size_t)row * (DIN / 4) + t] = make_uint2(h0, h1);
    out_lo[(size_t)row * (DIN / 4) + t] = make_uint2(l0, l1);
}

// ---------------- launch ----------------
extern "C" void kernel_launch(void* const* d_in, const int* in_sizes, int n_in,
                              void* d_out, int out_size) {
    const float* x_seq      = (const float*)d_in[0];
    const float* in_proj_w  = (const float*)d_in[1];
    const float* conv_w     = (const float*)d_in[2];
    const float* conv_b     = (const float*)d_in[3];
    const float* dt_bias    = (const float*)d_in[4];
    const float* A_log      = (const float*)d_in[5];
    const float* Dv         = (const float*)d_in[6];
    const float* norm_w     = (const float*)d_in[7];
    const float* out_proj_w = (const float*)d_in[8];
    float* out = (float*)d_out;

    float *zx, *xbc, *dtp, *acum, *states, *prefix, *y;
    uint2 *ah, *al, *wh, *wl;
    cudaGetSymbolAddress((void**)&zx, g_zx);
    cudaGetSymbolAddress((void**)&xbc, g_xbc);
    cudaGetSymbolAddress((void**)&dtp, g_dt);
    cudaGetSymbolAddress((void**)&acum, g_acum);
    cudaGetSymbolAddress((void**)&states, g_states);
    cudaGetSymbolAddress((void**)&prefix, g_prefix);
    cudaGetSymbolAddress((void**)&y, g_y);
    cudaGetSymbolAddress((void**)&ah, g_act_hi);
    cudaGetSymbolAddress((void**)&al, g_act_lo);
    cudaGetSymbolAddress((void**)&wh, g_w_hi);
    cudaGetSymbolAddress((void**)&wl, g_w_lo);

    // ---- in_proj ----
    int n4x = NTOK * DMODEL / 4;
    int n4w1 = DPROJ * DMODEL / 4;
    split_kernel<<<n4x / 256, 256>>>((const float4*)x_seq, ah, al, n4x);
    split_kernel<<<(n4w1 + 255) / 256, 256>>>((const float4*)in_proj_w, wh, wl, n4w1);
    gemm_bf16ld<<<dim3((DPROJ + 127) / 128, NTOK / 128), 256>>>(
        (const uint16_t*)ah, (const uint16_t*)al, (const uint16_t*)wh, (const uint16_t*)wl,
        zx, NTOK, DPROJ, DMODEL);

    conv_kernel<<<(NTOK / 4 * CONVDIM) / 256, 256>>>(zx, conv_w, conv_b, xbc);
    dt_acum_kernel<<<dim3(B_SZ * NCH, NH), CHUNK>>>(zx, dt_bias, A_log, dtp, acum);
    ydiag_mma<<<dim3(B_SZ * NCH, NH, 4), 128, 49152>>>(xbc, dtp, acum, y);
    states_mma<<<dim3(B_SZ * NCH, NH), 128>>>(xbc, dtp, acum, states);
    scan_kernel<<<dim3(B_SZ, NH), 256>>>(acum, states, prefix);
    yoff_mma<<<dim3(B_SZ * NCH, NH, 4), 128>>>(xbc, prefix, acum, Dv, y);
    // gate+norm emits bf16 hi/lo of gated-normed y directly into act buffers
    gate_norm_kernel<<<NTOK, 256>>>(zx, norm_w, y, ah, al);

    // ---- out_proj ----
    int n4w2 = DMODEL * DIN / 4;
    split_kernel<<<n4w2 / 256, 256>>>((const float4*)out_proj_w, wh, wl, n4w2);
    gemm_bf16ld<<<dim3(DMODEL / 128, NTOK / 128), 256>>>(
        (const uint16_t*)ah, (const uint16_t*)al, (const uint16_t*)wh, (const uint16_t*)wl,
        out, NTOK, DMODEL, DIN);
}

// round 15
// speedup vs baseline: 1.2235x; 1.2235x over previous
#include <cuda_runtime.h>
#include <math.h>
#include <stdint.h>

#define B_SZ   4
#define SEQ    4096
#define DMODEL 512
#define DIN    1024
#define NH     16
#define HD     64
#define DS     64
#define NCH    16
#define CHUNK  256
#define CONVDIM 1152
#define DPROJ  2192
#define NTOK   (B_SZ*SEQ)   // 16384

// ---------------- scratch (device globals; no runtime alloc) ----------------
__device__ float g_zx[(size_t)NTOK*DPROJ];
__device__ float g_xbc[(size_t)NTOK*CONVDIM];
__device__ float g_dt[NTOK*NH];
__device__ float g_acum[B_SZ*NCH*NH*CHUNK];
__device__ float g_states[B_SZ*NCH*NH*HD*DS];
__device__ float g_prefix[B_SZ*NCH*NH*HD*DS];
__device__ float g_y[(size_t)NTOK*DIN];
__device__ uint2 g_act_hi[(size_t)NTOK*DIN/4];
__device__ uint2 g_act_lo[(size_t)NTOK*DIN/4];
__device__ uint2 g_w_hi[(DPROJ*DMODEL)/4];
__device__ uint2 g_w_lo[(DPROJ*DMODEL)/4];

// ---------------- tf32 helpers (SSD kernels) ----------------
__device__ __forceinline__ uint32_t cvt_tf32(float f) {
    uint32_t r; asm("cvt.rna.tf32.f32 %0, %1;" : "=r"(r) : "f"(f)); return r;
}
__device__ __forceinline__ float tf32r(float f) { return __uint_as_float(cvt_tf32(f)); }

__device__ __forceinline__ void mma8(float* c, const float* a, const float* b) {
    asm volatile("mma.sync.aligned.m16n8k8.row.col.f32.tf32.tf32.f32 "
        "{%0,%1,%2,%3}, {%4,%5,%6,%7}, {%8,%9}, {%0,%1,%2,%3};"
        : "+f"(c[0]), "+f"(c[1]), "+f"(c[2]), "+f"(c[3])
        : "r"(__float_as_uint(a[0])), "r"(__float_as_uint(a[1])),
          "r"(__float_as_uint(a[2])), "r"(__float_as_uint(a[3])),
          "r"(__float_as_uint(b[0])), "r"(__float_as_uint(b[1])));
}
__device__ __forceinline__ void mma_bf16(float* c, const uint32_t* a, const uint32_t* b) {
    asm volatile("mma.sync.aligned.m16n8k16.row.col.f32.bf16.bf16.f32 "
        "{%0,%1,%2,%3}, {%4,%5,%6,%7}, {%8,%9}, {%0,%1,%2,%3};"
        : "+f"(c[0]), "+f"(c[1]), "+f"(c[2]), "+f"(c[3])
        : "r"(a[0]), "r"(a[1]), "r"(a[2]), "r"(a[3]), "r"(b[0]), "r"(b[1]));
}

__device__ __forceinline__ void bsplit2(float2 p, uint32_t& hi, uint32_t& lo) {
    uint32_t ux = __float_as_uint(p.x), uy = __float_as_uint(p.y);
    hi = __byte_perm(ux, uy, 0x7632);
    float rx = p.x - __uint_as_float(ux & 0xffff0000u);
    float ry = p.y - __uint_as_float(uy & 0xffff0000u);
    lo = __byte_perm(__float_as_uint(rx), __float_as_uint(ry), 0x7632);
}

__device__ __forceinline__ int sw64(int r, int c) {
    return r * 64 + ((((c >> 2) ^ (r & 7)) << 2) | (c & 3));
}
__device__ __forceinline__ uint32_t smem_u32(const void* p) {
    uint32_t a;
    asm("{ .reg .u64 t; cvta.to.shared.u64 t, %1; cvt.u32.u64 %0, t; }" : "=r"(a) : "l"(p));
    return a;
}
#define LDSM4(r0,r1,r2,r3,addr) \
    asm volatile("ldmatrix.sync.aligned.m8n8.x4.shared.b16 {%0,%1,%2,%3}, [%4];" \
        : "=r"(r0), "=r"(r1), "=r"(r2), "=r"(r3) : "r"(addr))

// ---------------- fp32 -> bf16 hi/lo split (grid-stride) ----------------
__global__ __launch_bounds__(512) void split_kernel(const float4* __restrict__ src,
                                                    uint2* __restrict__ hi,
                                                    uint2* __restrict__ lo, int n4) {
    for (int i = blockIdx.x * 512 + threadIdx.x; i < n4; i += gridDim.x * 512) {
        float4 v = src[i];
        uint32_t h0, l0, h1, l1;
        bsplit2(make_float2(v.x, v.y), h0, l0);
        bsplit2(make_float2(v.z, v.w), h1, l1);
        hi[i] = make_uint2(h0, h1);
        lo[i] = make_uint2(l0, l1);
    }
}

// ======= bf16 GEMM with pre-split inputs (R12 proven geometry): C = A @ B^T =======
// tiles: BM=128, BN=64, BK=32, 2-stage cp.async, 256 threads. smem exactly 48KB.
// stage layout (bytes): Ahi[128x64B]=8K, Alo=8K, Bhi[64x64B]=4K, Blo=4K -> 24K/stage.
// chunk swizzle: 16B chunk c of row r stored at r*64 + ((c ^ ((r>>1)&3))<<4).
__global__ __launch_bounds__(256) void gemm_bf16ld(const uint16_t* __restrict__ Ahi,
                                                   const uint16_t* __restrict__ Alo,
                                                   const uint16_t* __restrict__ Bhi,
                                                   const uint16_t* __restrict__ Blo,
                                                   float* __restrict__ C,
                                                   int M, int N, int K) {
    __shared__ char smem[49152];
    uint32_t sb0 = smem_u32(smem);
    int tid = threadIdx.x, lane = tid & 31, wid = tid >> 5;
    int wm = wid >> 1, wn = wid & 1;
    int g = lane >> 2, tg = lane & 3;
    int rowBase = blockIdx.y * 128, colBase = blockIdx.x * 64;

    int sel = lane >> 3;
    int rowoff = ((sel & 1) << 3) + (lane & 7);
    int chsel = sel >> 1;

    float acc[2][4][4];
#pragma unroll
    for (int i = 0; i < 2; i++)
#pragma unroll
        for (int j = 0; j < 4; j++)
#pragma unroll
            for (int q = 0; q < 4; q++) acc[i][j][q] = 0.f;

    int KT = K >> 5;
    auto loadTile = [&](int buf, int k0) {
        uint32_t base = sb0 + buf * 24576;
#pragma unroll
        for (int q = 0; q < 2; q++) {
            int i = tid + q * 256;
            int r = i >> 2, c = i & 3;
            uint32_t off = (uint32_t)(r * 64 + ((c ^ ((r >> 1) & 3)) << 4));
            const uint16_t* sh = &Ahi[(size_t)(rowBase + r) * K + k0 + c * 8];
            const uint16_t* sl = &Alo[(size_t)(rowBase + r) * K + k0 + c * 8];
            asm volatile("cp.async.ca.shared.global [%0], [%1], 16;" :: "r"(base + off), "l"(sh));
            asm volatile("cp.async.ca.shared.global [%0], [%1], 16;" :: "r"(base + 8192 + off), "l"(sl));
        }
        {
            int i = tid;
            int r = i >> 2, c = i & 3;
            int nrow = colBase + r;
            uint32_t off = (uint32_t)(r * 64 + ((c ^ ((r >> 1) & 3)) << 4));
            const uint16_t* sh = &Bhi[(size_t)(nrow < N ? nrow : 0) * K + k0 + c * 8];
            const uint16_t* sl = &Blo[(size_t)(nrow < N ? nrow : 0) * K + k0 + c * 8];
            int sz = (nrow < N) ? 16 : 0;
            asm volatile("cp.async.ca.shared.global [%0], [%1], 16, %2;" :: "r"(base + 16384 + off), "l"(sh), "r"(sz));
            asm volatile("cp.async.ca.shared.global [%0], [%1], 16, %2;" :: "r"(base + 20480 + off), "l"(sl), "r"(sz));
        }
        asm volatile("cp.async.commit_group;");
    };

    loadTile(0, 0);
    for (int kt = 0; kt < KT; kt++) {
        if (kt + 1 < KT) {
            loadTile((kt + 1) & 1, (kt + 1) * 32);
            asm volatile("cp.async.wait_group 1;");
        } else {
            asm volatile("cp.async.wait_group 0;");
        }
        __syncthreads();
        uint32_t base = sb0 + (kt & 1) * 24576;
#pragma unroll
        for (int kb16 = 0; kb16 < 2; kb16++) {
            int cbase = kb16 * 2;
            int ch = cbase + chsel;
            uint32_t ah[2][4], al[2][4];
#pragma unroll
            for (int tm = 0; tm < 2; tm++) {
                int r = wm * 32 + tm * 16 + rowoff;
                uint32_t off = (uint32_t)(r * 64 + ((ch ^ ((r >> 1) & 3)) << 4));
                LDSM4(ah[tm][0], ah[tm][1], ah[tm][2], ah[tm][3], base + off);
                LDSM4(al[tm][0], al[tm][1], al[tm][2], al[tm][3], base + 8192 + off);
            }
            uint32_t bh[4][2], bl[4][2];
#pragma unroll
            for (int pr = 0; pr < 2; pr++) {
                int r = wn * 32 + pr * 16 + rowoff;
                uint32_t off = (uint32_t)(r * 64 + ((ch ^ ((r >> 1) & 3)) << 4));
                uint32_t t0, t1, t2, t3;
                LDSM4(t0, t1, t2, t3, base + 16384 + off);
                bh[pr * 2][0] = t0; bh[pr * 2 + 1][0] = t1;
                bh[pr * 2][1] = t2; bh[pr * 2 + 1][1] = t3;
                LDSM4(t0, t1, t2, t3, base + 20480 + off);
                bl[pr * 2][0] = t0; bl[pr * 2 + 1][0] = t1;
                bl[pr * 2][1] = t2; bl[pr * 2 + 1][1] = t3;
            }
#pragma unroll
            for (int tm = 0; tm < 2; tm++)
#pragma unroll
                for (int tn = 0; tn < 4; tn++) {
                    mma_bf16(acc[tm][tn], ah[tm], bh[tn]);
                    mma_bf16(acc[tm][tn], ah[tm], bl[tn]);
                    mma_bf16(acc[tm][tn], al[tm], bh[tn]);
                }
        }
        __syncthreads();
    }
#pragma unroll
    for (int tm = 0; tm < 2; tm++) {
        int r0 = rowBase + wm * 32 + tm * 16;
#pragma unroll
        for (int tn = 0; tn < 4; tn++) {
            int c0 = colBase + wn * 32 + tn * 8 + tg * 2;
            if (c0 < N) {
                *(float2*)&C[(size_t)(r0 + g) * N + c0]     = make_float2(acc[tm][tn][0], acc[tm][tn][1]);
                *(float2*)&C[(size_t)(r0 + g + 8) * N + c0] = make_float2(acc[tm][tn][2], acc[tm][tn][3]);
            }
        }
    }
}

// ---------------- causal conv1d (width 4) + SiLU, sliding-window ----------------
__global__ __launch_bounds__(256) void conv_kernel(const float* __restrict__ zx,
                                                   const float* __restrict__ conv_w,
                                                   const float* __restrict__ conv_b,
                                                   float* __restrict__ xbc) {
    int idx = blockIdx.x * 256 + threadIdx.x;
    int c = idx % CONVDIM;
    int bl4 = idx / CONVDIM;
    int b = bl4 / (SEQ / 4);
    int l0 = (bl4 % (SEQ / 4)) * 4;

    float w0 = conv_w[c * 4 + 0], w1 = conv_w[c * 4 + 1];
    float w2 = conv_w[c * 4 + 2], w3 = conv_w[c * 4 + 3];
    float bias = conv_b[c];

    float v[7];
#pragma unroll
    for (int k = 0; k < 7; k++) {
        int ls = l0 - 3 + k;
        v[k] = (ls >= 0) ? zx[(size_t)(b * SEQ + ls) * DPROJ + DIN + c] : 0.f;
    }
#pragma unroll
    for (int j = 0; j < 4; j++) {
        float a = bias + v[j] * w0 + v[j + 1] * w1 + v[j + 2] * w2 + v[j + 3] * w3;
        xbc[(size_t)(b * SEQ + l0 + j) * CONVDIM + c] = a / (1.f + __expf(-a));
    }
}

// ---------------- dt softplus + per-chunk cumsum of dt*A ----------------
__global__ __launch_bounds__(256) void dt_acum_kernel(const float* __restrict__ zx,
                                                      const float* __restrict__ dt_bias,
                                                      const float* __restrict__ A_log,
                                                      float* __restrict__ dtp,
                                                      float* __restrict__ acum) {
    int bc = blockIdx.x;
    int h = blockIdx.y;
    int b = bc >> 4, c = bc & 15;
    int l = threadIdx.x;
    int row = b * SEQ + c * CHUNK + l;
    float x = zx[(size_t)row * DPROJ + (DPROJ - NH) + h] + dt_bias[h];
    float dtv = (x > 20.f) ? x : log1pf(expf(x));
    dtp[row * NH + h] = dtv;
    float a = -expf(A_log[h]) * dtv;

    __shared__ float s[CHUNK];
    s[l] = a;
    __syncthreads();
#pragma unroll
    for (int off = 1; off < CHUNK; off <<= 1) {
        float v = (l >= off) ? s[l - off] : 0.f;
        __syncthreads();
        s[l] += v;
        __syncthreads();
    }
    acum[(bc * NH + h) * CHUNK + l] = s[l];
}

// =================== MMA intra-chunk Y_diag, 64x64 tiles ===================
__global__ __launch_bounds__(128) void ydiag_mma(const float* __restrict__ xbc,
                                                 const float* __restrict__ dtp,
                                                 const float* __restrict__ acum,
                                                 float* __restrict__ y) {
    extern __shared__ float sm[];
    float* sB = sm;
    float* sX = sm + 4096;
    float* sS = sm + 8192;

    int bc = blockIdx.x, h = blockIdx.y, lt = blockIdx.z;
    int b = bc >> 4, c = bc & 15;
    int rowBase = b * SEQ + c * CHUNK;
    int tid = threadIdx.x, lane = tid & 31, w = tid >> 5;
    int g = lane >> 2, tg = lane & 3;
    int lbase = lt * 64;
    const float* acbase = &acum[(bc * NH + h) * CHUNK];

    float creg[8][4];
    {
        const float* c0 = &xbc[(size_t)(rowBase + lbase + w * 16 + g) * CONVDIM + DIN + DS];
        const float* c1 = &xbc[(size_t)(rowBase + lbase + w * 16 + g + 8) * CONVDIM + DIN + DS];
#pragma unroll
        for (int kb8 = 0; kb8 < 8; kb8++) {
            int kb = kb8 * 8;
            creg[kb8][0] = tf32r(c0[kb + tg]);
            creg[kb8][1] = tf32r(c1[kb + tg]);
            creg[kb8][2] = tf32r(c0[kb + tg + 4]);
            creg[kb8][3] = tf32r(c1[kb + tg + 4]);
        }
    }
    float aL0 = acbase[lbase + w * 16 + g];
    float aL1 = acbase[lbase + w * 16 + g + 8];
    int lg0 = lbase + w * 16 + g, lg1 = lg0 + 8;

    float accY[8][4];
#pragma unroll
    for (int nt = 0; nt < 8; nt++)
#pragma unroll
        for (int q = 0; q < 4; q++) accY[nt][q] = 0.f;

    for (int st = 0; st <= lt; st++) {
        __syncthreads();
        int sbase = st * 64;
        for (int i = tid; i < 64 * 16; i += 128) {
            int r = i >> 4, q = (i & 15) * 4;
            size_t grow = (size_t)(rowBase + sbase + r);
            float4 bv = *(const float4*)&xbc[grow * CONVDIM + DIN + q];
            float4 bt = make_float4(tf32r(bv.x), tf32r(bv.y), tf32r(bv.z), tf32r(bv.w));
            *(float4*)&sB[r * 64 + ((((q >> 2) ^ (r & 7)) << 2))] = bt;
            float dtv = dtp[grow * NH + h];
            float4 xv = *(const float4*)&xbc[grow * CONVDIM + h * HD + q];
            float4 xt = make_float4(tf32r(xv.x * dtv), tf32r(xv.y * dtv),
                                    tf32r(xv.z * dtv), tf32r(xv.w * dtv));
            *(float4*)&sX[r * 64 + ((((q >> 2) ^ (r & 7)) << 2))] = xt;
        }
        __syncthreads();

        float accS[8][4];
#pragma unroll
        for (int nt = 0; nt < 8; nt++)
#pragma unroll
            for (int q = 0; q < 4; q++) accS[nt][q] = 0.f;
#pragma unroll
        for (int kb8 = 0; kb8 < 8; kb8++) {
            int kb = kb8 * 8;
#pragma unroll
            for (int nt = 0; nt < 8; nt++) {
                float bf[2] = { sB[sw64(nt * 8 + g, kb + tg)],
                                sB[sw64(nt * 8 + g, kb + tg + 4)] };
                mma8(accS[nt], creg[kb8], bf);
            }
        }
#pragma unroll
        for (int nt = 0; nt < 8; nt++) {
            int col0 = nt * 8 + 2 * tg;
            int s0 = sbase + col0, s1 = s0 + 1;
            float as0 = __ldg(&acbase[s0]), as1 = __ldg(&acbase[s1]);
            float w00 = (s0 <= lg0) ? __expf(aL0 - as0) : 0.f;
            float w01 = (s1 <= lg0) ? __expf(aL0 - as1) : 0.f;
            float w10 = (s0 <= lg1) ? __expf(aL1 - as0) : 0.f;
            float w11 = (s1 <= lg1) ? __expf(aL1 - as1) : 0.f;
            *(float2*)&sS[sw64(w * 16 + g, col0)] =
                make_float2(tf32r(accS[nt][0] * w00), tf32r(accS[nt][1] * w01));
            *(float2*)&sS[sw64(w * 16 + g + 8, col0)] =
                make_float2(tf32r(accS[nt][2] * w10), tf32r(accS[nt][3] * w11));
        }
        __syncwarp();

#pragma unroll
        for (int kb8 = 0; kb8 < 8; kb8++) {
            int kb = kb8 * 8;
            float a[4];
            a[0] = sS[sw64(w * 16 + g, kb + tg)];
            a[1] = sS[sw64(w * 16 + g + 8, kb + tg)];
            a[2] = sS[sw64(w * 16 + g, kb + tg + 4)];
            a[3] = sS[sw64(w * 16 + g + 8, kb + tg + 4)];
#pragma unroll
            for (int nt = 0; nt < 8; nt++) {
                float bf[2] = { sX[sw64(kb + tg, nt * 8 + g)],
                                sX[sw64(kb + tg + 4, nt * 8 + g)] };
                mma8(accY[nt], a, bf);
            }
        }
    }
    size_t r0 = (size_t)(rowBase + lbase + w * 16 + g);
#pragma unroll
    for (int nt = 0; nt < 8; nt++) {
        int col = h * HD + nt * 8 + 2 * tg;
        *(float2*)&y[r0 * DIN + col]       = make_float2(accY[nt][0], accY[nt][1]);
        *(float2*)&y[(r0 + 8) * DIN + col] = make_float2(accY[nt][2], accY[nt][3]);
    }
}

// =================== MMA per-chunk states ===================
__global__ __launch_bounds__(128) void states_mma(const float* __restrict__ xbc,
                                                  const float* __restrict__ dtp,
                                                  const float* __restrict__ acum,
                                                  float* __restrict__ states) {
    __shared__ float sX[4096];
    __shared__ float sB[4096];

    int bc = blockIdx.x, h = blockIdx.y;
    int b = bc >> 4, c = bc & 15;
    int rowBase = b * SEQ + c * CHUNK;
    int tid = threadIdx.x, lane = tid & 31, w = tid >> 5;
    int g = lane >> 2, tg = lane & 3;
    int m0 = w * 16;
    const float* acbase = &acum[(bc * NH + h) * CHUNK];
    float aEnd = acbase[CHUNK - 1];

    float acc[8][4];
#pragma unroll
    for (int nt = 0; nt < 8; nt++)
#pragma unroll
        for (int q = 0; q < 4; q++) acc[nt][q] = 0.f;

    for (int st = 0; st < 4; st++) {
        __syncthreads();
        int sbase = st * 64;
        for (int i = tid; i < 64 * 16; i += 128) {
            int r = i >> 4, q = (i & 15) * 4;
            size_t grow = (size_t)(rowBase + sbase + r);
            float dec = __expf(aEnd - acbase[sbase + r]);
            float dtv = dtp[grow * NH + h] * dec;
            float4 xv = *(const float4*)&xbc[grow * CONVDIM + h * HD + q];
            float4 xt = make_float4(tf32r(xv.x * dtv), tf32r(xv.y * dtv),
                                    tf32r(xv.z * dtv), tf32r(xv.w * dtv));
            *(float4*)&sX[r * 64 + ((((q >> 2) ^ (r & 7)) << 2))] = xt;
            float4 bv = *(const float4*)&xbc[grow * CONVDIM + DIN + q];
            float4 bt = make_float4(tf32r(bv.x), tf32r(bv.y), tf32r(bv.z), tf32r(bv.w));
            *(float4*)&sB[r * 64 + ((((q >> 2) ^ (r & 7)) << 2))] = bt;
        }
        __syncthreads();
#pragma unroll
        for (int kb8 = 0; kb8 < 8; kb8++) {
            int kb = kb8 * 8;
            float a[4];
            a[0] = sX[sw64(kb + tg, m0 + g)];
            a[1] = sX[sw64(kb + tg, m0 + g + 8)];
            a[2] = sX[sw64(kb + tg + 4, m0 + g)];
            a[3] = sX[sw64(kb + tg + 4, m0 + g + 8)];
#pragma unroll
            for (int nt = 0; nt < 8; nt++) {
                float bf[2] = { sB[sw64(nt * 8 + g, kb + tg)],
                                sB[sw64(nt * 8 + g, kb + tg + 4)] };
                mma8(acc[nt], a, bf);
            }
        }
    }
    size_t base = (size_t)(bc * NH + h) * (HD * DS);
#pragma unroll
    for (int nt = 0; nt < 8; nt++) {
        int col = nt * 8 + 2 * tg;
        *(float2*)&states[base + (m0 + g) * DS + col]     = make_float2(acc[nt][0], acc[nt][1]);
        *(float2*)&states[base + (m0 + g + 8) * DS + col] = make_float2(acc[nt][2], acc[nt][3]);
    }
}

// ---------------- inter-chunk sequential scan ----------------
__global__ __launch_bounds__(256) void scan_kernel(const float* __restrict__ acum,
                                                   const float* __restrict__ states,
                                                   float* __restrict__ prefix) {
    int b = blockIdx.x, h = blockIdx.y, t = threadIdx.x;
    float S[16];
#pragma unroll
    for (int j = 0; j < 16; j++) S[j] = 0.f;
    for (int c = 0; c < NCH; c++) {
        size_t base = ((size_t)((b * NCH + c) * NH + h)) * (HD * DS) + t * 16;
#pragma unroll
        for (int j = 0; j < 16; j += 4) {
            float4 v = make_float4(S[j], S[j + 1], S[j + 2], S[j + 3]);
            *(float4*)&prefix[base + j] = v;
        }
        float cs = __expf(acum[((b * NCH + c) * NH + h) * CHUNK + (CHUNK - 1)]);
#pragma unroll
        for (int j = 0; j < 16; j += 4) {
            float4 sv = *(const float4*)&states[base + j];
            S[j + 0] = cs * S[j + 0] + sv.x;
            S[j + 1] = cs * S[j + 1] + sv.y;
            S[j + 2] = cs * S[j + 2] + sv.z;
            S[j + 3] = cs * S[j + 3] + sv.w;
        }
    }
}

// =================== MMA Y_off + D*xh ===================
__global__ __launch_bounds__(128) void yoff_mma(const float* __restrict__ xbc,
                                                const float* __restrict__ prefix,
                                                const float* __restrict__ acum,
                                                const float* __restrict__ Dv,
                                                float* __restrict__ y) {
    __shared__ float sP[4096];

    int bc = blockIdx.x, h = blockIdx.y, lt = blockIdx.z;
    int b = bc >> 4, c = bc & 15;
    int rowBase = b * SEQ + c * CHUNK;
    int tid = threadIdx.x, lane = tid & 31, w = tid >> 5;
    int g = lane >> 2, tg = lane & 3;
    int lbase = lt * 64;

    size_t pbase = (size_t)(bc * NH + h) * (HD * DS);
    for (int i = tid; i < 64 * 16; i += 128) {
        int r = i >> 4, q = (i & 15) * 4;
        float4 v = *(const float4*)&prefix[pbase + r * DS + q];
        float4 vt = make_float4(tf32r(v.x), tf32r(v.y), tf32r(v.z), tf32r(v.w));
        *(float4*)&sP[r * 64 + ((((q >> 2) ^ (r & 7)) << 2))] = vt;
    }

    float creg[8][4];
    {
        const float* c0 = &xbc[(size_t)(rowBase + lbase + w * 16 + g) * CONVDIM + DIN + DS];
        const float* c1 = &xbc[(size_t)(rowBase + lbase + w * 16 + g + 8) * CONVDIM + DIN + DS];
#pragma unroll
        for (int kb8 = 0; kb8 < 8; kb8++) {
            int kb = kb8 * 8;
            creg[kb8][0] = tf32r(c0[kb + tg]);
            creg[kb8][1] = tf32r(c1[kb + tg]);
            creg[kb8][2] = tf32r(c0[kb + tg + 4]);
            creg[kb8][3] = tf32r(c1[kb + tg + 4]);
        }
    }
    __syncthreads();

    float acc[8][4];
#pragma unroll
    for (int nt = 0; nt < 8; nt++)
#pragma unroll
        for (int q = 0; q < 4; q++) acc[nt][q] = 0.f;

#pragma unroll
    for (int kb8 = 0; kb8 < 8; kb8++) {
        int kb = kb8 * 8;
#pragma unroll
        for (int nt = 0; nt < 8; nt++) {
            float bf[2] = { sP[sw64(nt * 8 + g, kb + tg)],
                            sP[sw64(nt * 8 + g, kb + tg + 4)] };
            mma8(acc[nt], creg[kb8], bf);
        }
    }

    float Dh = Dv[h];
    float ae0 = __expf(acum[(bc * NH + h) * CHUNK + lbase + w * 16 + g]);
    float ae1 = __expf(acum[(bc * NH + h) * CHUNK + lbase + w * 16 + g + 8]);
    size_t grow = (size_t)(rowBase + lbase + w * 16 + g);
#pragma unroll
    for (int nt = 0; nt < 8; nt++) {
        int col = h * HD + nt * 8 + 2 * tg;
        float2 yv0 = *(float2*)&y[grow * DIN + col];
        float2 xh0 = *(const float2*)&xbc[grow * CONVDIM + col];
        float2 yv1 = *(float2*)&y[(grow + 8) * DIN + col];
        float2 xh1 = *(const float2*)&xbc[(grow + 8) * CONVDIM + col];
        yv0.x += ae0 * acc[nt][0] + Dh * xh0.x;
        yv0.y += ae0 * acc[nt][1] + Dh * xh0.y;
        yv1.x += ae1 * acc[nt][2] + Dh * xh1.x;
        yv1.y += ae1 * acc[nt][3] + Dh * xh1.y;
        *(float2*)&y[grow * DIN + col] = yv0;
        *(float2*)&y[(grow + 8) * DIN + col] = yv1;
    }
}

// ---------------- gate + RMSNorm, emitting bf16 hi/lo directly ----------------
__global__ __launch_bounds__(256) void gate_norm_kernel(const float* __restrict__ zx,
                                                        const float* __restrict__ norm_w,
                                                        const float* __restrict__ y,
                                                        uint2* __restrict__ out_hi,
                                                        uint2* __restrict__ out_lo) {
    int row = blockIdx.x;
    int t = threadIdx.x;
    float4 yv = ((const float4*)&y[(size_t)row * DIN])[t];
    float4 zv = ((const float4*)&zx[(size_t)row * DPROJ])[t];
    float g0 = yv.x * (zv.x / (1.f + __expf(-zv.x)));
    float g1 = yv.y * (zv.y / (1.f + __expf(-zv.y)));
    float g2 = yv.z * (zv.z / (1.f + __expf(-zv.z)));
    float g3 = yv.w * (zv.w / (1.f + __expf(-zv.w)));
    float ss = g0 * g0 + g1 * g1 + g2 * g2 + g3 * g3;
#pragma unroll
    for (int o = 16; o; o >>= 1) ss += __shfl_xor_sync(0xffffffffu, ss, o);
    __shared__ float red[8];
    if ((t & 31) == 0) red[t >> 5] = ss;
    __syncthreads();
    float tot = red[0] + red[1] + red[2] + red[3] + red[4] + red[5] + red[6] + red[7];
    float rms = rsqrtf(tot / (float)DIN + 1e-5f);
    float4 nw = ((const float4*)norm_w)[t];
    float o0 = g0 * rms * nw.x, o1 = g1 * rms * nw.y;
    float o2 = g2 * rms * nw.z, o3 = g3 * rms * nw.w;
    uint32_t h0, l0, h1, l1;
    bsplit2(make_float2(o0, o1), h0, l0);
    bsplit2(make_float2(o2, o3), h1, l1);
    out_hi[(size_t)row * (DIN / 4) + t] = make_uint2(h0, h1);
    out_lo[(size_t)row * (DIN / 4) + t] = make_uint2(l0, l1);
}

// ---------------- launch ----------------
extern "C" void kernel_launch(void* const* d_in, const int* in_sizes, int n_in,
                              void* d_out, int out_size) {
    const float* x_seq      = (const float*)d_in[0];
    const float* in_proj_w  = (const float*)d_in[1];
    const float* conv_w     = (const float*)d_in[2];
    const float* conv_b     = (const float*)d_in[3];
    const float* dt_bias    = (const float*)d_in[4];
    const float* A_log      = (const float*)d_in[5];
    const float* Dv         = (const float*)d_in[6];
    const float* norm_w     = (const float*)d_in[7];
    const float* out_proj_w = (const float*)d_in[8];
    float* out = (float*)d_out;

    float *zx, *xbc, *dtp, *acum, *states, *prefix, *y;
    uint2 *ah, *al, *wh, *wl;
    cudaGetSymbolAddress((void**)&zx, g_zx);
    cudaGetSymbolAddress((void**)&xbc, g_xbc);
    cudaGetSymbolAddress((void**)&dtp, g_dt);
    cudaGetSymbolAddress((void**)&acum, g_acum);
    cudaGetSymbolAddress((void**)&states, g_states);
    cudaGetSymbolAddress((void**)&prefix, g_prefix);
    cudaGetSymbolAddress((void**)&y, g_y);
    cudaGetSymbolAddress((void**)&ah, g_act_hi);
    cudaGetSymbolAddress((void**)&al, g_act_lo);
    cudaGetSymbolAddress((void**)&wh, g_w_hi);
    cudaGetSymbolAddress((void**)&wl, g_w_lo);

    // ---- in_proj ----
    int n4x = NTOK * DMODEL / 4;
    int n4w1 = DPROJ * DMODEL / 4;
    split_kernel<<<592, 512>>>((const float4*)x_seq, ah, al, n4x);
    split_kernel<<<592, 512>>>((const float4*)in_proj_w, wh, wl, n4w1);
    gemm_bf16ld<<<dim3((DPROJ + 63) / 64, NTOK / 128), 256>>>(
        (const uint16_t*)ah, (const uint16_t*)al, (const uint16_t*)wh, (const uint16_t*)wl,
        zx, NTOK, DPROJ, DMODEL);

    conv_kernel<<<(NTOK / 4 * CONVDIM) / 256, 256>>>(zx, conv_w, conv_b, xbc);
    dt_acum_kernel<<<dim3(B_SZ * NCH, NH), CHUNK>>>(zx, dt_bias, A_log, dtp, acum);
    ydiag_mma<<<dim3(B_SZ * NCH, NH, 4), 128, 49152>>>(xbc, dtp, acum, y);
    states_mma<<<dim3(B_SZ * NCH, NH), 128>>>(xbc, dtp, acum, states);
    scan_kernel<<<dim3(B_SZ, NH), 256>>>(acum, states, prefix);
    yoff_mma<<<dim3(B_SZ * NCH, NH, 4), 128>>>(xbc, prefix, acum, Dv, y);
    // gate+norm emits bf16 hi/lo of gated-normed y directly into act buffers
    gate_norm_kernel<<<NTOK, 256>>>(zx, norm_w, y, ah, al);

    // ---- out_proj ----
    int n4w2 = DMODEL * DIN / 4;
    split_kernel<<<592, 512>>>((const float4*)out_proj_w, wh, wl, n4w2);
    gemm_bf16ld<<<dim3(DMODEL / 64, NTOK / 128), 256>>>(
        (const uint16_t*)ah, (const uint16_t*)al, (const uint16_t*)wh, (const uint16_t*)wl,
        out, NTOK, DMODEL, DIN);
}

// round 16
// speedup vs baseline: 1.2377x; 1.0116x over previous
#include <cuda_runtime.h>
#include <math.h>
#include <stdint.h>

#define B_SZ   4
#define SEQ    4096
#define DMODEL 512
#define DIN    1024
#define NH     16
#define HD     64
#define DS     64
#define NCH    16
#define CHUNK  256
#define CONVDIM 1152
#define DPROJ  2192
#define NTOK   (B_SZ*SEQ)   // 16384

// ---------------- scratch (device globals; no runtime alloc) ----------------
__device__ float g_zx[(size_t)NTOK*DPROJ];
__device__ float g_xbc[(size_t)NTOK*CONVDIM];
__device__ float g_dt[NTOK*NH];
__device__ float g_acum[B_SZ*NCH*NH*CHUNK];
__device__ float g_states[B_SZ*NCH*NH*HD*DS];
__device__ float g_prefix[B_SZ*NCH*NH*HD*DS];
__device__ float g_y[(size_t)NTOK*DIN];
__device__ uint2 g_act_hi[(size_t)NTOK*DIN/4];
__device__ uint2 g_act_lo[(size_t)NTOK*DIN/4];
__device__ uint2 g_w_hi[(DPROJ*DMODEL)/4];
__device__ uint2 g_w_lo[(DPROJ*DMODEL)/4];

// ---------------- tf32 helpers (SSD kernels) ----------------
__device__ __forceinline__ uint32_t cvt_tf32(float f) {
    uint32_t r; asm("cvt.rna.tf32.f32 %0, %1;" : "=r"(r) : "f"(f)); return r;
}
__device__ __forceinline__ float tf32r(float f) { return __uint_as_float(cvt_tf32(f)); }

__device__ __forceinline__ void mma8(float* c, const float* a, const float* b) {
    asm volatile("mma.sync.aligned.m16n8k8.row.col.f32.tf32.tf32.f32 "
        "{%0,%1,%2,%3}, {%4,%5,%6,%7}, {%8,%9}, {%0,%1,%2,%3};"
        : "+f"(c[0]), "+f"(c[1]), "+f"(c[2]), "+f"(c[3])
        : "r"(__float_as_uint(a[0])), "r"(__float_as_uint(a[1])),
          "r"(__float_as_uint(a[2])), "r"(__float_as_uint(a[3])),
          "r"(__float_as_uint(b[0])), "r"(__float_as_uint(b[1])));
}
__device__ __forceinline__ void mma_bf16(float* c, const uint32_t* a, const uint32_t* b) {
    asm volatile("mma.sync.aligned.m16n8k16.row.col.f32.bf16.bf16.f32 "
        "{%0,%1,%2,%3}, {%4,%5,%6,%7}, {%8,%9}, {%0,%1,%2,%3};"
        : "+f"(c[0]), "+f"(c[1]), "+f"(c[2]), "+f"(c[3])
        : "r"(a[0]), "r"(a[1]), "r"(a[2]), "r"(a[3]), "r"(b[0]), "r"(b[1]));
}

__device__ __forceinline__ void bsplit2(float2 p, uint32_t& hi, uint32_t& lo) {
    uint32_t ux = __float_as_uint(p.x), uy = __float_as_uint(p.y);
    hi = __byte_perm(ux, uy, 0x7632);
    float rx = p.x - __uint_as_float(ux & 0xffff0000u);
    float ry = p.y - __uint_as_float(uy & 0xffff0000u);
    lo = __byte_perm(__float_as_uint(rx), __float_as_uint(ry), 0x7632);
}

__device__ __forceinline__ int sw64(int r, int c) {
    return r * 64 + ((((c >> 2) ^ (r & 7)) << 2) | (c & 3));
}
__device__ __forceinline__ uint32_t smem_u32(const void* p) {
    uint32_t a;
    asm("{ .reg .u64 t; cvta.to.shared.u64 t, %1; cvt.u32.u64 %0, t; }" : "=r"(a) : "l"(p));
    return a;
}
#define LDSM4(r0,r1,r2,r3,addr) \
    asm volatile("ldmatrix.sync.aligned.m8n8.x4.shared.b16 {%0,%1,%2,%3}, [%4];" \
        : "=r"(r0), "=r"(r1), "=r"(r2), "=r"(r3) : "r"(addr))

// ---------------- fp32 -> bf16 hi/lo split (grid-stride) ----------------
__global__ __launch_bounds__(512) void split_kernel(const float4* __restrict__ src,
                                                    uint2* __restrict__ hi,
                                                    uint2* __restrict__ lo, int n4) {
    for (int i = blockIdx.x * 512 + threadIdx.x; i < n4; i += gridDim.x * 512) {
        float4 v = src[i];
        uint32_t h0, l0, h1, l1;
        bsplit2(make_float2(v.x, v.y), h0, l0);
        bsplit2(make_float2(v.z, v.w), h1, l1);
        hi[i] = make_uint2(h0, h1);
        lo[i] = make_uint2(l0, l1);
    }
}

// ======= bf16 GEMM, pre-split inputs: C = A @ B^T (hi*hi + hi*lo + lo*hi) =======
// BM=64, BN=64, BK=32, 3-STAGE cp.async, ONE sync/iter, 128 threads (4 warps, m32xn32).
// stage (16KB): Ahi[64x64B]=4K @0, Alo @4K, Bhi @8K, Blo @12K; 3 stages = 48KB.
// chunk swizzle: 16B chunk c of row r stored at r*64 + ((c ^ ((r>>1)&3))<<4).
__global__ __launch_bounds__(128) void gemm_bf16ld(const uint16_t* __restrict__ Ahi,
                                                   const uint16_t* __restrict__ Alo,
                                                   const uint16_t* __restrict__ Bhi,
                                                   const uint16_t* __restrict__ Blo,
                                                   float* __restrict__ C,
                                                   int M, int N, int K) {
    __shared__ char smem[49152];
    uint32_t sb0 = smem_u32(smem);
    int tid = threadIdx.x, lane = tid & 31, wid = tid >> 5;
    int wm = wid >> 1, wn = wid & 1;        // warp grid 2x2
    int g = lane >> 2, tg = lane & 3;
    int rowBase = blockIdx.y * 64, colBase = blockIdx.x * 64;

    int sel = lane >> 3;
    int rowoff = ((sel & 1) << 3) + (lane & 7);
    int chsel = sel >> 1;

    float acc[2][4][4];
#pragma unroll
    for (int i = 0; i < 2; i++)
#pragma unroll
        for (int j = 0; j < 4; j++)
#pragma unroll
            for (int q = 0; q < 4; q++) acc[i][j][q] = 0.f;

    int KT = K >> 5;
    auto loadTile = [&](int buf, int k0) {
        uint32_t base = sb0 + buf * 16384;
        // A: 64 rows x 4 chunks = 256 chunk-positions; 2 per thread (hi + lo each)
#pragma unroll
        for (int q = 0; q < 2; q++) {
            int i = tid + q * 128;
            int r = i >> 2, c = i & 3;
            uint32_t off = (uint32_t)(r * 64 + ((c ^ ((r >> 1) & 3)) << 4));
            const uint16_t* sh = &Ahi[(size_t)(rowBase + r) * K + k0 + c * 8];
            const uint16_t* sl = &Alo[(size_t)(rowBase + r) * K + k0 + c * 8];
            asm volatile("cp.async.ca.shared.global [%0], [%1], 16;" :: "r"(base + off), "l"(sh));
            asm volatile("cp.async.ca.shared.global [%0], [%1], 16;" :: "r"(base + 4096 + off), "l"(sl));
        }
        // B: 64 rows x 4 chunks, predicated on n < N
#pragma unroll
        for (int q = 0; q < 2; q++) {
            int i = tid + q * 128;
            int r = i >> 2, c = i & 3;
            int nrow = colBase + r;
            uint32_t off = (uint32_t)(r * 64 + ((c ^ ((r >> 1) & 3)) << 4));
            const uint16_t* sh = &Bhi[(size_t)(nrow < N ? nrow : 0) * K + k0 + c * 8];
            const uint16_t* sl = &Blo[(size_t)(nrow < N ? nrow : 0) * K + k0 + c * 8];
            int sz = (nrow < N) ? 16 : 0;
            asm volatile("cp.async.ca.shared.global [%0], [%1], 16, %2;" :: "r"(base + 8192 + off), "l"(sh), "r"(sz));
            asm volatile("cp.async.ca.shared.global [%0], [%1], 16, %2;" :: "r"(base + 12288 + off), "l"(sl), "r"(sz));
        }
        asm volatile("cp.async.commit_group;");
    };

    loadTile(0, 0);
    if (KT > 1) loadTile(1, 32);
    for (int kt = 0; kt < KT; kt++) {
        if (kt + 1 < KT) {
            asm volatile("cp.async.wait_group 1;");
        } else {
            asm volatile("cp.async.wait_group 0;");
        }
        __syncthreads();     // single sync per iteration (3-stage)
        uint32_t base = sb0 + (kt % 3) * 16384;
#pragma unroll
        for (int kb16 = 0; kb16 < 2; kb16++) {
            int ch = kb16 * 2 + chsel;
            uint32_t ah[2][4], al[2][4];
#pragma unroll
            for (int tm = 0; tm < 2; tm++) {
                int r = wm * 32 + tm * 16 + rowoff;
                uint32_t off = (uint32_t)(r * 64 + ((ch ^ ((r >> 1) & 3)) << 4));
                LDSM4(ah[tm][0], ah[tm][1], ah[tm][2], ah[tm][3], base + off);
                LDSM4(al[tm][0], al[tm][1], al[tm][2], al[tm][3], base + 4096 + off);
            }
            uint32_t bh[4][2], bl[4][2];
#pragma unroll
            for (int pr = 0; pr < 2; pr++) {
                int r = wn * 32 + pr * 16 + rowoff;
                uint32_t off = (uint32_t)(r * 64 + ((ch ^ ((r >> 1) & 3)) << 4));
                uint32_t t0, t1, t2, t3;
                LDSM4(t0, t1, t2, t3, base + 8192 + off);
                bh[pr * 2][0] = t0; bh[pr * 2 + 1][0] = t1;
                bh[pr * 2][1] = t2; bh[pr * 2 + 1][1] = t3;
                LDSM4(t0, t1, t2, t3, base + 12288 + off);
                bl[pr * 2][0] = t0; bl[pr * 2 + 1][0] = t1;
                bl[pr * 2][1] = t2; bl[pr * 2 + 1][1] = t3;
            }
#pragma unroll
            for (int tm = 0; tm < 2; tm++)
#pragma unroll
                for (int tn = 0; tn < 4; tn++) {
                    mma_bf16(acc[tm][tn], ah[tm], bh[tn]);
                    mma_bf16(acc[tm][tn], ah[tm], bl[tn]);
                    mma_bf16(acc[tm][tn], al[tm], bh[tn]);
                }
        }
        if (kt + 2 < KT) loadTile((kt + 2) % 3, (kt + 2) * 32);
    }
#pragma unroll
    for (int tm = 0; tm < 2; tm++) {
        int r0 = rowBase + wm * 32 + tm * 16;
#pragma unroll
        for (int tn = 0; tn < 4; tn++) {
            int c0 = colBase + wn * 32 + tn * 8 + tg * 2;
            if (c0 < N) {
                *(float2*)&C[(size_t)(r0 + g) * N + c0]     = make_float2(acc[tm][tn][0], acc[tm][tn][1]);
                *(float2*)&C[(size_t)(r0 + g + 8) * N + c0] = make_float2(acc[tm][tn][2], acc[tm][tn][3]);
            }
        }
    }
}

// ---------------- causal conv1d (width 4) + SiLU, sliding-window ----------------
__global__ __launch_bounds__(256) void conv_kernel(const float* __restrict__ zx,
                                                   const float* __restrict__ conv_w,
                                                   const float* __restrict__ conv_b,
                                                   float* __restrict__ xbc) {
    int idx = blockIdx.x * 256 + threadIdx.x;
    int c = idx % CONVDIM;
    int bl4 = idx / CONVDIM;
    int b = bl4 / (SEQ / 4);
    int l0 = (bl4 % (SEQ / 4)) * 4;

    float w0 = conv_w[c * 4 + 0], w1 = conv_w[c * 4 + 1];
    float w2 = conv_w[c * 4 + 2], w3 = conv_w[c * 4 + 3];
    float bias = conv_b[c];

    float v[7];
#pragma unroll
    for (int k = 0; k < 7; k++) {
        int ls = l0 - 3 + k;
        v[k] = (ls >= 0) ? zx[(size_t)(b * SEQ + ls) * DPROJ + DIN + c] : 0.f;
    }
#pragma unroll
    for (int j = 0; j < 4; j++) {
        float a = bias + v[j] * w0 + v[j + 1] * w1 + v[j + 2] * w2 + v[j + 3] * w3;
        xbc[(size_t)(b * SEQ + l0 + j) * CONVDIM + c] = a / (1.f + __expf(-a));
    }
}

// ---------------- dt softplus + per-chunk cumsum of dt*A ----------------
__global__ __launch_bounds__(256) void dt_acum_kernel(const float* __restrict__ zx,
                                                      const float* __restrict__ dt_bias,
                                                      const float* __restrict__ A_log,
                                                      float* __restrict__ dtp,
                                                      float* __restrict__ acum) {
    int bc = blockIdx.x;
    int h = blockIdx.y;
    int b = bc >> 4, c = bc & 15;
    int l = threadIdx.x;
    int row = b * SEQ + c * CHUNK + l;
    float x = zx[(size_t)row * DPROJ + (DPROJ - NH) + h] + dt_bias[h];
    float dtv = (x > 20.f) ? x : log1pf(expf(x));
    dtp[row * NH + h] = dtv;
    float a = -expf(A_log[h]) * dtv;

    __shared__ float s[CHUNK];
    s[l] = a;
    __syncthreads();
#pragma unroll
    for (int off = 1; off < CHUNK; off <<= 1) {
        float v = (l >= off) ? s[l - off] : 0.f;
        __syncthreads();
        s[l] += v;
        __syncthreads();
    }
    acum[(bc * NH + h) * CHUNK + l] = s[l];
}

// =================== MMA intra-chunk Y_diag, 64x64 tiles ===================
__global__ __launch_bounds__(128) void ydiag_mma(const float* __restrict__ xbc,
                                                 const float* __restrict__ dtp,
                                                 const float* __restrict__ acum,
                                                 float* __restrict__ y) {
    extern __shared__ float sm[];
    float* sB = sm;
    float* sX = sm + 4096;
    float* sS = sm + 8192;

    int bc = blockIdx.x, h = blockIdx.y, lt = blockIdx.z;
    int b = bc >> 4, c = bc & 15;
    int rowBase = b * SEQ + c * CHUNK;
    int tid = threadIdx.x, lane = tid & 31, w = tid >> 5;
    int g = lane >> 2, tg = lane & 3;
    int lbase = lt * 64;
    const float* acbase = &acum[(bc * NH + h) * CHUNK];

    float creg[8][4];
    {
        const float* c0 = &xbc[(size_t)(rowBase + lbase + w * 16 + g) * CONVDIM + DIN + DS];
        const float* c1 = &xbc[(size_t)(rowBase + lbase + w * 16 + g + 8) * CONVDIM + DIN + DS];
#pragma unroll
        for (int kb8 = 0; kb8 < 8; kb8++) {
            int kb = kb8 * 8;
            creg[kb8][0] = tf32r(c0[kb + tg]);
            creg[kb8][1] = tf32r(c1[kb + tg]);
            creg[kb8][2] = tf32r(c0[kb + tg + 4]);
            creg[kb8][3] = tf32r(c1[kb + tg + 4]);
        }
    }
    float aL0 = acbase[lbase + w * 16 + g];
    float aL1 = acbase[lbase + w * 16 + g + 8];
    int lg0 = lbase + w * 16 + g, lg1 = lg0 + 8;

    float accY[8][4];
#pragma unroll
    for (int nt = 0; nt < 8; nt++)
#pragma unroll
        for (int q = 0; q < 4; q++) accY[nt][q] = 0.f;

    for (int st = 0; st <= lt; st++) {
        __syncthreads();
        int sbase = st * 64;
        for (int i = tid; i < 64 * 16; i += 128) {
            int r = i >> 4, q = (i & 15) * 4;
            size_t grow = (size_t)(rowBase + sbase + r);
            float4 bv = *(const float4*)&xbc[grow * CONVDIM + DIN + q];
            float4 bt = make_float4(tf32r(bv.x), tf32r(bv.y), tf32r(bv.z), tf32r(bv.w));
            *(float4*)&sB[r * 64 + ((((q >> 2) ^ (r & 7)) << 2))] = bt;
            float dtv = dtp[grow * NH + h];
            float4 xv = *(const float4*)&xbc[grow * CONVDIM + h * HD + q];
            float4 xt = make_float4(tf32r(xv.x * dtv), tf32r(xv.y * dtv),
                                    tf32r(xv.z * dtv), tf32r(xv.w * dtv));
            *(float4*)&sX[r * 64 + ((((q >> 2) ^ (r & 7)) << 2))] = xt;
        }
        __syncthreads();

        float accS[8][4];
#pragma unroll
        for (int nt = 0; nt < 8; nt++)
#pragma unroll
            for (int q = 0; q < 4; q++) accS[nt][q] = 0.f;
#pragma unroll
        for (int kb8 = 0; kb8 < 8; kb8++) {
            int kb = kb8 * 8;
#pragma unroll
            for (int nt = 0; nt < 8; nt++) {
                float bf[2] = { sB[sw64(nt * 8 + g, kb + tg)],
                                sB[sw64(nt * 8 + g, kb + tg + 4)] };
                mma8(accS[nt], creg[kb8], bf);
            }
        }
#pragma unroll
        for (int nt = 0; nt < 8; nt++) {
            int col0 = nt * 8 + 2 * tg;
            int s0 = sbase + col0, s1 = s0 + 1;
            float as0 = __ldg(&acbase[s0]), as1 = __ldg(&acbase[s1]);
            float w00 = (s0 <= lg0) ? __expf(aL0 - as0) : 0.f;
            float w01 = (s1 <= lg0) ? __expf(aL0 - as1) : 0.f;
            float w10 = (s0 <= lg1) ? __expf(aL1 - as0) : 0.f;
            float w11 = (s1 <= lg1) ? __expf(aL1 - as1) : 0.f;
            *(float2*)&sS[sw64(w * 16 + g, col0)] =
                make_float2(tf32r(accS[nt][0] * w00), tf32r(accS[nt][1] * w01));
            *(float2*)&sS[sw64(w * 16 + g + 8, col0)] =
                make_float2(tf32r(accS[nt][2] * w10), tf32r(accS[nt][3] * w11));
        }
        __syncwarp();

#pragma unroll
        for (int kb8 = 0; kb8 < 8; kb8++) {
            int kb = kb8 * 8;
            float a[4];
            a[0] = sS[sw64(w * 16 + g, kb + tg)];
            a[1] = sS[sw64(w * 16 + g + 8, kb + tg)];
            a[2] = sS[sw64(w * 16 + g, kb + tg + 4)];
            a[3] = sS[sw64(w * 16 + g + 8, kb + tg + 4)];
#pragma unroll
            for (int nt = 0; nt < 8; nt++) {
                float bf[2] = { sX[sw64(kb + tg, nt * 8 + g)],
                                sX[sw64(kb + tg + 4, nt * 8 + g)] };
                mma8(accY[nt], a, bf);
            }
        }
    }
    size_t r0 = (size_t)(rowBase + lbase + w * 16 + g);
#pragma unroll
    for (int nt = 0; nt < 8; nt++) {
        int col = h * HD + nt * 8 + 2 * tg;
        *(float2*)&y[r0 * DIN + col]       = make_float2(accY[nt][0], accY[nt][1]);
        *(float2*)&y[(r0 + 8) * DIN + col] = make_float2(accY[nt][2], accY[nt][3]);
    }
}

// =================== MMA per-chunk states ===================
__global__ __launch_bounds__(128) void states_mma(const float* __restrict__ xbc,
                                                  const float* __restrict__ dtp,
                                                  const float* __restrict__ acum,
                                                  float* __restrict__ states) {
    __shared__ float sX[4096];
    __shared__ float sB[4096];

    int bc = blockIdx.x, h = blockIdx.y;
    int b = bc >> 4, c = bc & 15;
    int rowBase = b * SEQ + c * CHUNK;
    int tid = threadIdx.x, lane = tid & 31, w = tid >> 5;
    int g = lane >> 2, tg = lane & 3;
    int m0 = w * 16;
    const float* acbase = &acum[(bc * NH + h) * CHUNK];
    float aEnd = acbase[CHUNK - 1];

    float acc[8][4];
#pragma unroll
    for (int nt = 0; nt < 8; nt++)
#pragma unroll
        for (int q = 0; q < 4; q++) acc[nt][q] = 0.f;

    for (int st = 0; st < 4; st++) {
        __syncthreads();
        int sbase = st * 64;
        for (int i = tid; i < 64 * 16; i += 128) {
            int r = i >> 4, q = (i & 15) * 4;
            size_t grow = (size_t)(rowBase + sbase + r);
            float dec = __expf(aEnd - acbase[sbase + r]);
            float dtv = dtp[grow * NH + h] * dec;
            float4 xv = *(const float4*)&xbc[grow * CONVDIM + h * HD + q];
            float4 xt = make_float4(tf32r(xv.x * dtv), tf32r(xv.y * dtv),
                                    tf32r(xv.z * dtv), tf32r(xv.w * dtv));
            *(float4*)&sX[r * 64 + ((((q >> 2) ^ (r & 7)) << 2))] = xt;
            float4 bv = *(const float4*)&xbc[grow * CONVDIM + DIN + q];
            float4 bt = make_float4(tf32r(bv.x), tf32r(bv.y), tf32r(bv.z), tf32r(bv.w));
            *(float4*)&sB[r * 64 + ((((q >> 2) ^ (r & 7)) << 2))] = bt;
        }
        __syncthreads();
#pragma unroll
        for (int kb8 = 0; kb8 < 8; kb8++) {
            int kb = kb8 * 8;
            float a[4];
            a[0] = sX[sw64(kb + tg, m0 + g)];
            a[1] = sX[sw64(kb + tg, m0 + g + 8)];
            a[2] = sX[sw64(kb + tg + 4, m0 + g)];
            a[3] = sX[sw64(kb + tg + 4, m0 + g + 8)];
#pragma unroll
            for (int nt = 0; nt < 8; nt++) {
                float bf[2] = { sB[sw64(nt * 8 + g, kb + tg)],
                                sB[sw64(nt * 8 + g, kb + tg + 4)] };
                mma8(acc[nt], a, bf);
            }
        }
    }
    size_t base = (size_t)(bc * NH + h) * (HD * DS);
#pragma unroll
    for (int nt = 0; nt < 8; nt++) {
        int col = nt * 8 + 2 * tg;
        *(float2*)&states[base + (m0 + g) * DS + col]     = make_float2(acc[nt][0], acc[nt][1]);
        *(float2*)&states[base + (m0 + g + 8) * DS + col] = make_float2(acc[nt][2], acc[nt][3]);
    }
}

// ---------------- inter-chunk sequential scan ----------------
__global__ __launch_bounds__(256) void scan_kernel(const float* __restrict__ acum,
                                                   const float* __restrict__ states,
                                                   float* __restrict__ prefix) {
    int b = blockIdx.x, h = blockIdx.y, t = threadIdx.x;
    float S[16];
#pragma unroll
    for (int j = 0; j < 16; j++) S[j] = 0.f;
    for (int c = 0; c < NCH; c++) {
        size_t base = ((size_t)((b * NCH + c) * NH + h)) * (HD * DS) + t * 16;
#pragma unroll
        for (int j = 0; j < 16; j += 4) {
            float4 v = make_float4(S[j], S[j + 1], S[j + 2], S[j + 3]);
            *(float4*)&prefix[base + j] = v;
        }
        float cs = __expf(acum[((b * NCH + c) * NH + h) * CHUNK + (CHUNK - 1)]);
#pragma unroll
        for (int j = 0; j < 16; j += 4) {
            float4 sv = *(const float4*)&states[base + j];
            S[j + 0] = cs * S[j + 0] + sv.x;
            S[j + 1] = cs * S[j + 1] + sv.y;
            S[j + 2] = cs * S[j + 2] + sv.z;
            S[j + 3] = cs * S[j + 3] + sv.w;
        }
    }
}

// =================== MMA Y_off + D*xh ===================
__global__ __launch_bounds__(128) void yoff_mma(const float* __restrict__ xbc,
                                                const float* __restrict__ prefix,
                                                const float* __restrict__ acum,
                                                const float* __restrict__ Dv,
                                                float* __restrict__ y) {
    __shared__ float sP[4096];

    int bc = blockIdx.x, h = blockIdx.y, lt = blockIdx.z;
    int b = bc >> 4, c = bc & 15;
    int rowBase = b * SEQ + c * CHUNK;
    int tid = threadIdx.x, lane = tid & 31, w = tid >> 5;
    int g = lane >> 2, tg = lane & 3;
    int lbase = lt * 64;

    size_t pbase = (size_t)(bc * NH + h) * (HD * DS);
    for (int i = tid; i < 64 * 16; i += 128) {
        int r = i >> 4, q = (i & 15) * 4;
        float4 v = *(const float4*)&prefix[pbase + r * DS + q];
        float4 vt = make_float4(tf32r(v.x), tf32r(v.y), tf32r(v.z), tf32r(v.w));
        *(float4*)&sP[r * 64 + ((((q >> 2) ^ (r & 7)) << 2))] = vt;
    }

    float creg[8][4];
    {
        const float* c0 = &xbc[(size_t)(rowBase + lbase + w * 16 + g) * CONVDIM + DIN + DS];
        const float* c1 = &xbc[(size_t)(rowBase + lbase + w * 16 + g + 8) * CONVDIM + DIN + DS];
#pragma unroll
        for (int kb8 = 0; kb8 < 8; kb8++) {
            int kb = kb8 * 8;
            creg[kb8][0] = tf32r(c0[kb + tg]);
            creg[kb8][1] = tf32r(c1[kb + tg]);
            creg[kb8][2] = tf32r(c0[kb + tg + 4]);
            creg[kb8][3] = tf32r(c1[kb + tg + 4]);
        }
    }
    __syncthreads();

    float acc[8][4];
#pragma unroll
    for (int nt = 0; nt < 8; nt++)
#pragma unroll
        for (int q = 0; q < 4; q++) acc[nt][q] = 0.f;

#pragma unroll
    for (int kb8 = 0; kb8 < 8; kb8++) {
        int kb = kb8 * 8;
#pragma unroll
        for (int nt = 0; nt < 8; nt++) {
            float bf[2] = { sP[sw64(nt * 8 + g, kb + tg)],
                            sP[sw64(nt * 8 + g, kb + tg + 4)] };
            mma8(acc[nt], creg[kb8], bf);
        }
    }

    float Dh = Dv[h];
    float ae0 = __expf(acum[(bc * NH + h) * CHUNK + lbase + w * 16 + g]);
    float ae1 = __expf(acum[(bc * NH + h) * CHUNK + lbase + w * 16 + g + 8]);
    size_t grow = (size_t)(rowBase + lbase + w * 16 + g);
#pragma unroll
    for (int nt = 0; nt < 8; nt++) {
        int col = h * HD + nt * 8 + 2 * tg;
        float2 yv0 = *(float2*)&y[grow * DIN + col];
        float2 xh0 = *(const float2*)&xbc[grow * CONVDIM + col];
        float2 yv1 = *(float2*)&y[(grow + 8) * DIN + col];
        float2 xh1 = *(const float2*)&xbc[(grow + 8) * CONVDIM + col];
        yv0.x += ae0 * acc[nt][0] + Dh * xh0.x;
        yv0.y += ae0 * acc[nt][1] + Dh * xh0.y;
        yv1.x += ae1 * acc[nt][2] + Dh * xh1.x;
        yv1.y += ae1 * acc[nt][3] + Dh * xh1.y;
        *(float2*)&y[grow * DIN + col] = yv0;
        *(float2*)&y[(grow + 8) * DIN + col] = yv1;
    }
}

// ---------------- gate + RMSNorm, emitting bf16 hi/lo directly ----------------
__global__ __launch_bounds__(256) void gate_norm_kernel(const float* __restrict__ zx,
                                                        const float* __restrict__ norm_w,
                                                        const float* __restrict__ y,
                                                        uint2* __restrict__ out_hi,
                                                        uint2* __restrict__ out_lo) {
    int row = blockIdx.x;
    int t = threadIdx.x;
    float4 yv = ((const float4*)&y[(size_t)row * DIN])[t];
    float4 zv = ((const float4*)&zx[(size_t)row * DPROJ])[t];
    float g0 = yv.x * (zv.x / (1.f + __expf(-zv.x)));
    float g1 = yv.y * (zv.y / (1.f + __expf(-zv.y)));
    float g2 = yv.z * (zv.z / (1.f + __expf(-zv.z)));
    float g3 = yv.w * (zv.w / (1.f + __expf(-zv.w)));
    float ss = g0 * g0 + g1 * g1 + g2 * g2 + g3 * g3;
#pragma unroll
    for (int o = 16; o; o >>= 1) ss += __shfl_xor_sync(0xffffffffu, ss, o);
    __shared__ float red[8];
    if ((t & 31) == 0) red[t >> 5] = ss;
    __syncthreads();
    float tot = red[0] + red[1] + red[2] + red[3] + red[4] + red[5] + red[6] + red[7];
    float rms = rsqrtf(tot / (float)DIN + 1e-5f);
    float4 nw = ((const float4*)norm_w)[t];
    float o0 = g0 * rms * nw.x, o1 = g1 * rms * nw.y;
    float o2 = g2 * rms * nw.z, o3 = g3 * rms * nw.w;
    uint32_t h0, l0, h1, l1;
    bsplit2(make_float2(o0, o1), h0, l0);
    bsplit2(make_float2(o2, o3), h1, l1);
    out_hi[(size_t)row * (DIN / 4) + t] = make_uint2(h0, h1);
    out_lo[(size_t)row * (DIN / 4) + t] = make_uint2(l0, l1);
}

// ---------------- launch ----------------
extern "C" void kernel_launch(void* const* d_in, const int* in_sizes, int n_in,
                              void* d_out, int out_size) {
    const float* x_seq      = (const float*)d_in[0];
    const float* in_proj_w  = (const float*)d_in[1];
    const float* conv_w     = (const float*)d_in[2];
    const float* conv_b     = (const float*)d_in[3];
    const float* dt_bias    = (const float*)d_in[4];
    const float* A_log      = (const float*)d_in[5];
    const float* Dv         = (const float*)d_in[6];
    const float* norm_w     = (const float*)d_in[7];
    const float* out_proj_w = (const float*)d_in[8];
    float* out = (float*)d_out;

    float *zx, *xbc, *dtp, *acum, *states, *prefix, *y;
    uint2 *ah, *al, *wh, *wl;
    cudaGetSymbolAddress((void**)&zx, g_zx);
    cudaGetSymbolAddress((void**)&xbc, g_xbc);
    cudaGetSymbolAddress((void**)&dtp, g_dt);
    cudaGetSymbolAddress((void**)&acum, g_acum);
    cudaGetSymbolAddress((void**)&states, g_states);
    cudaGetSymbolAddress((void**)&prefix, g_prefix);
    cudaGetSymbolAddress((void**)&y, g_y);
    cudaGetSymbolAddress((void**)&ah, g_act_hi);
    cudaGetSymbolAddress((void**)&al, g_act_lo);
    cudaGetSymbolAddress((void**)&wh, g_w_hi);
    cudaGetSymbolAddress((void**)&wl, g_w_lo);

    // ---- in_proj ----
    int n4x = NTOK * DMODEL / 4;
    int n4w1 = DPROJ * DMODEL / 4;
    split_kernel<<<592, 512>>>((const float4*)x_seq, ah, al, n4x);
    split_kernel<<<592, 512>>>((const float4*)in_proj_w, wh, wl, n4w1);
    gemm_bf16ld<<<dim3((DPROJ + 63) / 64, NTOK / 64), 128>>>(
        (const uint16_t*)ah, (const uint16_t*)al, (const uint16_t*)wh, (const uint16_t*)wl,
        zx, NTOK, DPROJ, DMODEL);

    conv_kernel<<<(NTOK / 4 * CONVDIM) / 256, 256>>>(zx, conv_w, conv_b, xbc);
    dt_acum_kernel<<<dim3(B_SZ * NCH, NH), CHUNK>>>(zx, dt_bias, A_log, dtp, acum);
    ydiag_mma<<<dim3(B_SZ * NCH, NH, 4), 128, 49152>>>(xbc, dtp, acum, y);
    states_mma<<<dim3(B_SZ * NCH, NH), 128>>>(xbc, dtp, acum, states);
    scan_kernel<<<dim3(B_SZ, NH), 256>>>(acum, states, prefix);
    yoff_mma<<<dim3(B_SZ * NCH, NH, 4), 128>>>(xbc, prefix, acum, Dv, y);
    gate_norm_kernel<<<NTOK, 256>>>(zx, norm_w, y, ah, al);

    // ---- out_proj ----
    int n4w2 = DMODEL * DIN / 4;
    split_kernel<<<592, 512>>>((const float4*)out_proj_w, wh, wl, n4w2);
    gemm_bf16ld<<<dim3(DMODEL / 64, NTOK / 64), 128>>>(
        (const uint16_t*)ah, (const uint16_t*)al, (const uint16_t*)wh, (const uint16_t*)wl,
        out, NTOK, DMODEL, DIN);
}

// round 17
// speedup vs baseline: 1.3121x; 1.0601x over previous
#include <cuda_runtime.h>
#include <math.h>
#include <stdint.h>

#define B_SZ   4
#define SEQ    4096
#define DMODEL 512
#define DIN    1024
#define NH     16
#define HD     64
#define DS     64
#define NCH    16
#define CHUNK  256
#define CONVDIM 1152
#define DPROJ  2192
#define NTOK   (B_SZ*SEQ)   // 16384

// ---------------- scratch (device globals; no runtime alloc) ----------------
__device__ float g_zx[(size_t)NTOK*DPROJ];
__device__ float g_xbc[(size_t)NTOK*CONVDIM];
__device__ float g_dt[NTOK*NH];
__device__ float g_acum[B_SZ*NCH*NH*CHUNK];
__device__ float g_states[B_SZ*NCH*NH*HD*DS];
__device__ float g_prefix[B_SZ*NCH*NH*HD*DS];
__device__ float g_y[(size_t)NTOK*DIN];
__device__ uint2 g_act_hi[(size_t)NTOK*DIN/4];
__device__ uint2 g_act_lo[(size_t)NTOK*DIN/4];
__device__ uint2 g_w_hi[(DPROJ*DMODEL)/4];
__device__ uint2 g_w_lo[(DPROJ*DMODEL)/4];

// ---------------- tf32 helpers (SSD kernels) ----------------
__device__ __forceinline__ uint32_t cvt_tf32(float f) {
    uint32_t r; asm("cvt.rna.tf32.f32 %0, %1;" : "=r"(r) : "f"(f)); return r;
}
__device__ __forceinline__ float tf32r(float f) { return __uint_as_float(cvt_tf32(f)); }

__device__ __forceinline__ void mma8(float* c, const float* a, const float* b) {
    asm volatile("mma.sync.aligned.m16n8k8.row.col.f32.tf32.tf32.f32 "
        "{%0,%1,%2,%3}, {%4,%5,%6,%7}, {%8,%9}, {%0,%1,%2,%3};"
        : "+f"(c[0]), "+f"(c[1]), "+f"(c[2]), "+f"(c[3])
        : "r"(__float_as_uint(a[0])), "r"(__float_as_uint(a[1])),
          "r"(__float_as_uint(a[2])), "r"(__float_as_uint(a[3])),
          "r"(__float_as_uint(b[0])), "r"(__float_as_uint(b[1])));
}
__device__ __forceinline__ void mma_bf16(float* c, const uint32_t* a, const uint32_t* b) {
    asm volatile("mma.sync.aligned.m16n8k16.row.col.f32.bf16.bf16.f32 "
        "{%0,%1,%2,%3}, {%4,%5,%6,%7}, {%8,%9}, {%0,%1,%2,%3};"
        : "+f"(c[0]), "+f"(c[1]), "+f"(c[2]), "+f"(c[3])
        : "r"(a[0]), "r"(a[1]), "r"(a[2]), "r"(a[3]), "r"(b[0]), "r"(b[1]));
}

__device__ __forceinline__ void bsplit2(float2 p, uint32_t& hi, uint32_t& lo) {
    uint32_t ux = __float_as_uint(p.x), uy = __float_as_uint(p.y);
    hi = __byte_perm(ux, uy, 0x7632);
    float rx = p.x - __uint_as_float(ux & 0xffff0000u);
    float ry = p.y - __uint_as_float(uy & 0xffff0000u);
    lo = __byte_perm(__float_as_uint(rx), __float_as_uint(ry), 0x7632);
}

__device__ __forceinline__ int sw64(int r, int c) {
    return r * 64 + ((((c >> 2) ^ (r & 7)) << 2) | (c & 3));
}
__device__ __forceinline__ uint32_t smem_u32(const void* p) {
    uint32_t a;
    asm("{ .reg .u64 t; cvta.to.shared.u64 t, %1; cvt.u32.u64 %0, t; }" : "=r"(a) : "l"(p));
    return a;
}
#define LDSM4(r0,r1,r2,r3,addr) \
    asm volatile("ldmatrix.sync.aligned.m8n8.x4.shared.b16 {%0,%1,%2,%3}, [%4];" \
        : "=r"(r0), "=r"(r1), "=r"(r2), "=r"(r3) : "r"(addr))

// ---------------- fp32 -> bf16 hi/lo split (grid-stride) ----------------
__global__ __launch_bounds__(512) void split_kernel(const float4* __restrict__ src,
                                                    uint2* __restrict__ hi,
                                                    uint2* __restrict__ lo, int n4) {
    for (int i = blockIdx.x * 512 + threadIdx.x; i < n4; i += gridDim.x * 512) {
        float4 v = src[i];
        uint32_t h0, l0, h1, l1;
        bsplit2(make_float2(v.x, v.y), h0, l0);
        bsplit2(make_float2(v.z, v.w), h1, l1);
        hi[i] = make_uint2(h0, h1);
        lo[i] = make_uint2(l0, l1);
    }
}

// ======= bf16 GEMM, pre-split inputs (R16 geometry, at MMA-issue floor) =======
__global__ __launch_bounds__(128) void gemm_bf16ld(const uint16_t* __restrict__ Ahi,
                                                   const uint16_t* __restrict__ Alo,
                                                   const uint16_t* __restrict__ Bhi,
                                                   const uint16_t* __restrict__ Blo,
                                                   float* __restrict__ C,
                                                   int M, int N, int K) {
    __shared__ char smem[49152];
    uint32_t sb0 = smem_u32(smem);
    int tid = threadIdx.x, lane = tid & 31, wid = tid >> 5;
    int wm = wid >> 1, wn = wid & 1;
    int g = lane >> 2, tg = lane & 3;
    int rowBase = blockIdx.y * 64, colBase = blockIdx.x * 64;

    int sel = lane >> 3;
    int rowoff = ((sel & 1) << 3) + (lane & 7);
    int chsel = sel >> 1;

    float acc[2][4][4];
#pragma unroll
    for (int i = 0; i < 2; i++)
#pragma unroll
        for (int j = 0; j < 4; j++)
#pragma unroll
            for (int q = 0; q < 4; q++) acc[i][j][q] = 0.f;

    int KT = K >> 5;
    auto loadTile = [&](int buf, int k0) {
        uint32_t base = sb0 + buf * 16384;
#pragma unroll
        for (int q = 0; q < 2; q++) {
            int i = tid + q * 128;
            int r = i >> 2, c = i & 3;
            uint32_t off = (uint32_t)(r * 64 + ((c ^ ((r >> 1) & 3)) << 4));
            const uint16_t* sh = &Ahi[(size_t)(rowBase + r) * K + k0 + c * 8];
            const uint16_t* sl = &Alo[(size_t)(rowBase + r) * K + k0 + c * 8];
            asm volatile("cp.async.ca.shared.global [%0], [%1], 16;" :: "r"(base + off), "l"(sh));
            asm volatile("cp.async.ca.shared.global [%0], [%1], 16;" :: "r"(base + 4096 + off), "l"(sl));
        }
#pragma unroll
        for (int q = 0; q < 2; q++) {
            int i = tid + q * 128;
            int r = i >> 2, c = i & 3;
            int nrow = colBase + r;
            uint32_t off = (uint32_t)(r * 64 + ((c ^ ((r >> 1) & 3)) << 4));
            const uint16_t* sh = &Bhi[(size_t)(nrow < N ? nrow : 0) * K + k0 + c * 8];
            const uint16_t* sl = &Blo[(size_t)(nrow < N ? nrow : 0) * K + k0 + c * 8];
            int sz = (nrow < N) ? 16 : 0;
            asm volatile("cp.async.ca.shared.global [%0], [%1], 16, %2;" :: "r"(base + 8192 + off), "l"(sh), "r"(sz));
            asm volatile("cp.async.ca.shared.global [%0], [%1], 16, %2;" :: "r"(base + 12288 + off), "l"(sl), "r"(sz));
        }
        asm volatile("cp.async.commit_group;");
    };

    loadTile(0, 0);
    if (KT > 1) loadTile(1, 32);
    for (int kt = 0; kt < KT; kt++) {
        if (kt + 1 < KT) {
            asm volatile("cp.async.wait_group 1;");
        } else {
            asm volatile("cp.async.wait_group 0;");
        }
        __syncthreads();
        uint32_t base = sb0 + (kt % 3) * 16384;
#pragma unroll
        for (int kb16 = 0; kb16 < 2; kb16++) {
            int ch = kb16 * 2 + chsel;
            uint32_t ah[2][4], al[2][4];
#pragma unroll
            for (int tm = 0; tm < 2; tm++) {
                int r = wm * 32 + tm * 16 + rowoff;
                uint32_t off = (uint32_t)(r * 64 + ((ch ^ ((r >> 1) & 3)) << 4));
                LDSM4(ah[tm][0], ah[tm][1], ah[tm][2], ah[tm][3], base + off);
                LDSM4(al[tm][0], al[tm][1], al[tm][2], al[tm][3], base + 4096 + off);
            }
            uint32_t bh[4][2], bl[4][2];
#pragma unroll
            for (int pr = 0; pr < 2; pr++) {
                int r = wn * 32 + pr * 16 + rowoff;
                uint32_t off = (uint32_t)(r * 64 + ((ch ^ ((r >> 1) & 3)) << 4));
                uint32_t t0, t1, t2, t3;
                LDSM4(t0, t1, t2, t3, base + 8192 + off);
                bh[pr * 2][0] = t0; bh[pr * 2 + 1][0] = t1;
                bh[pr * 2][1] = t2; bh[pr * 2 + 1][1] = t3;
                LDSM4(t0, t1, t2, t3, base + 12288 + off);
                bl[pr * 2][0] = t0; bl[pr * 2 + 1][0] = t1;
                bl[pr * 2][1] = t2; bl[pr * 2 + 1][1] = t3;
            }
#pragma unroll
            for (int tm = 0; tm < 2; tm++)
#pragma unroll
                for (int tn = 0; tn < 4; tn++) {
                    mma_bf16(acc[tm][tn], ah[tm], bh[tn]);
                    mma_bf16(acc[tm][tn], ah[tm], bl[tn]);
                    mma_bf16(acc[tm][tn], al[tm], bh[tn]);
                }
        }
        if (kt + 2 < KT) loadTile((kt + 2) % 3, (kt + 2) * 32);
    }
#pragma unroll
    for (int tm = 0; tm < 2; tm++) {
        int r0 = rowBase + wm * 32 + tm * 16;
#pragma unroll
        for (int tn = 0; tn < 4; tn++) {
            int c0 = colBase + wn * 32 + tn * 8 + tg * 2;
            if (c0 < N) {
                *(float2*)&C[(size_t)(r0 + g) * N + c0]     = make_float2(acc[tm][tn][0], acc[tm][tn][1]);
                *(float2*)&C[(size_t)(r0 + g + 8) * N + c0] = make_float2(acc[tm][tn][2], acc[tm][tn][3]);
            }
        }
    }
}

// ---------------- causal conv1d (width 4) + SiLU, sliding-window ----------------
__global__ __launch_bounds__(256) void conv_kernel(const float* __restrict__ zx,
                                                   const float* __restrict__ conv_w,
                                                   const float* __restrict__ conv_b,
                                                   float* __restrict__ xbc) {
    int idx = blockIdx.x * 256 + threadIdx.x;
    int c = idx % CONVDIM;
    int bl4 = idx / CONVDIM;
    int b = bl4 / (SEQ / 4);
    int l0 = (bl4 % (SEQ / 4)) * 4;

    float w0 = conv_w[c * 4 + 0], w1 = conv_w[c * 4 + 1];
    float w2 = conv_w[c * 4 + 2], w3 = conv_w[c * 4 + 3];
    float bias = conv_b[c];

    float v[7];
#pragma unroll
    for (int k = 0; k < 7; k++) {
        int ls = l0 - 3 + k;
        v[k] = (ls >= 0) ? zx[(size_t)(b * SEQ + ls) * DPROJ + DIN + c] : 0.f;
    }
#pragma unroll
    for (int j = 0; j < 4; j++) {
        float a = bias + v[j] * w0 + v[j + 1] * w1 + v[j + 2] * w2 + v[j + 3] * w3;
        xbc[(size_t)(b * SEQ + l0 + j) * CONVDIM + c] = a / (1.f + __expf(-a));
    }
}

// ---------------- dt softplus + per-chunk cumsum of dt*A ----------------
__global__ __launch_bounds__(256) void dt_acum_kernel(const float* __restrict__ zx,
                                                      const float* __restrict__ dt_bias,
                                                      const float* __restrict__ A_log,
                                                      float* __restrict__ dtp,
                                                      float* __restrict__ acum) {
    int bc = blockIdx.x;
    int h = blockIdx.y;
    int b = bc >> 4, c = bc & 15;
    int l = threadIdx.x;
    int row = b * SEQ + c * CHUNK + l;
    float x = zx[(size_t)row * DPROJ + (DPROJ - NH) + h] + dt_bias[h];
    float dtv = (x > 20.f) ? x : log1pf(expf(x));
    dtp[row * NH + h] = dtv;
    float a = -expf(A_log[h]) * dtv;

    __shared__ float s[CHUNK];
    s[l] = a;
    __syncthreads();
#pragma unroll
    for (int off = 1; off < CHUNK; off <<= 1) {
        float v = (l >= off) ? s[l - off] : 0.f;
        __syncthreads();
        s[l] += v;
        __syncthreads();
    }
    acum[(bc * NH + h) * CHUNK + l] = s[l];
}

// =================== MMA intra-chunk Y_diag + FUSED Y_off + D*xh ===================
// accY starts as exp(ac_l) * C @ P^T (P loaded into sB buffer), then causal terms added.
__global__ __launch_bounds__(128) void ydiag_mma(const float* __restrict__ xbc,
                                                 const float* __restrict__ dtp,
                                                 const float* __restrict__ acum,
                                                 const float* __restrict__ prefix,
                                                 const float* __restrict__ Dv,
                                                 float* __restrict__ y) {
    extern __shared__ float sm[];
    float* sB = sm;
    float* sX = sm + 4096;
    float* sS = sm + 8192;

    int bc = blockIdx.x, h = blockIdx.y, lt = blockIdx.z;
    int b = bc >> 4, c = bc & 15;
    int rowBase = b * SEQ + c * CHUNK;
    int tid = threadIdx.x, lane = tid & 31, w = tid >> 5;
    int g = lane >> 2, tg = lane & 3;
    int lbase = lt * 64;
    const float* acbase = &acum[(bc * NH + h) * CHUNK];

    float creg[8][4];
    {
        const float* c0 = &xbc[(size_t)(rowBase + lbase + w * 16 + g) * CONVDIM + DIN + DS];
        const float* c1 = &xbc[(size_t)(rowBase + lbase + w * 16 + g + 8) * CONVDIM + DIN + DS];
#pragma unroll
        for (int kb8 = 0; kb8 < 8; kb8++) {
            int kb = kb8 * 8;
            creg[kb8][0] = tf32r(c0[kb + tg]);
            creg[kb8][1] = tf32r(c1[kb + tg]);
            creg[kb8][2] = tf32r(c0[kb + tg + 4]);
            creg[kb8][3] = tf32r(c1[kb + tg + 4]);
        }
    }
    float aL0 = acbase[lbase + w * 16 + g];
    float aL1 = acbase[lbase + w * 16 + g + 8];
    int lg0 = lbase + w * 16 + g, lg1 = lg0 + 8;

    // ---- fused Y_off: load P into sB, accY = C @ P^T, scale by exp(ac_l) ----
    float accY[8][4];
#pragma unroll
    for (int nt = 0; nt < 8; nt++)
#pragma unroll
        for (int q = 0; q < 4; q++) accY[nt][q] = 0.f;

    {
        size_t pbase = (size_t)(bc * NH + h) * (HD * DS);
        for (int i = tid; i < 64 * 16; i += 128) {
            int r = i >> 4, q = (i & 15) * 4;
            float4 v = *(const float4*)&prefix[pbase + r * DS + q];
            float4 vt = make_float4(tf32r(v.x), tf32r(v.y), tf32r(v.z), tf32r(v.w));
            *(float4*)&sB[r * 64 + ((((q >> 2) ^ (r & 7)) << 2))] = vt;
        }
        __syncthreads();
#pragma unroll
        for (int kb8 = 0; kb8 < 8; kb8++) {
            int kb = kb8 * 8;
#pragma unroll
            for (int nt = 0; nt < 8; nt++) {
                float bf[2] = { sB[sw64(nt * 8 + g, kb + tg)],
                                sB[sw64(nt * 8 + g, kb + tg + 4)] };
                mma8(accY[nt], creg[kb8], bf);
            }
        }
        float ae0 = __expf(aL0), ae1 = __expf(aL1);
#pragma unroll
        for (int nt = 0; nt < 8; nt++) {
            accY[nt][0] *= ae0; accY[nt][1] *= ae0;
            accY[nt][2] *= ae1; accY[nt][3] *= ae1;
        }
    }

    // ---- causal diag accumulation ----
    for (int st = 0; st <= lt; st++) {
        __syncthreads();
        int sbase = st * 64;
        for (int i = tid; i < 64 * 16; i += 128) {
            int r = i >> 4, q = (i & 15) * 4;
            size_t grow = (size_t)(rowBase + sbase + r);
            float4 bv = *(const float4*)&xbc[grow * CONVDIM + DIN + q];
            float4 bt = make_float4(tf32r(bv.x), tf32r(bv.y), tf32r(bv.z), tf32r(bv.w));
            *(float4*)&sB[r * 64 + ((((q >> 2) ^ (r & 7)) << 2))] = bt;
            float dtv = dtp[grow * NH + h];
            float4 xv = *(const float4*)&xbc[grow * CONVDIM + h * HD + q];
            float4 xt = make_float4(tf32r(xv.x * dtv), tf32r(xv.y * dtv),
                                    tf32r(xv.z * dtv), tf32r(xv.w * dtv));
            *(float4*)&sX[r * 64 + ((((q >> 2) ^ (r & 7)) << 2))] = xt;
        }
        __syncthreads();

        float accS[8][4];
#pragma unroll
        for (int nt = 0; nt < 8; nt++)
#pragma unroll
            for (int q = 0; q < 4; q++) accS[nt][q] = 0.f;
#pragma unroll
        for (int kb8 = 0; kb8 < 8; kb8++) {
            int kb = kb8 * 8;
#pragma unroll
            for (int nt = 0; nt < 8; nt++) {
                float bf[2] = { sB[sw64(nt * 8 + g, kb + tg)],
                                sB[sw64(nt * 8 + g, kb + tg + 4)] };
                mma8(accS[nt], creg[kb8], bf);
            }
        }
#pragma unroll
        for (int nt = 0; nt < 8; nt++) {
            int col0 = nt * 8 + 2 * tg;
            int s0 = sbase + col0, s1 = s0 + 1;
            float as0 = __ldg(&acbase[s0]), as1 = __ldg(&acbase[s1]);
            float w00 = (s0 <= lg0) ? __expf(aL0 - as0) : 0.f;
            float w01 = (s1 <= lg0) ? __expf(aL0 - as1) : 0.f;
            float w10 = (s0 <= lg1) ? __expf(aL1 - as0) : 0.f;
            float w11 = (s1 <= lg1) ? __expf(aL1 - as1) : 0.f;
            *(float2*)&sS[sw64(w * 16 + g, col0)] =
                make_float2(tf32r(accS[nt][0] * w00), tf32r(accS[nt][1] * w01));
            *(float2*)&sS[sw64(w * 16 + g + 8, col0)] =
                make_float2(tf32r(accS[nt][2] * w10), tf32r(accS[nt][3] * w11));
        }
        __syncwarp();

#pragma unroll
        for (int kb8 = 0; kb8 < 8; kb8++) {
            int kb = kb8 * 8;
            float a[4];
            a[0] = sS[sw64(w * 16 + g, kb + tg)];
            a[1] = sS[sw64(w * 16 + g + 8, kb + tg)];
            a[2] = sS[sw64(w * 16 + g, kb + tg + 4)];
            a[3] = sS[sw64(w * 16 + g + 8, kb + tg + 4)];
#pragma unroll
            for (int nt = 0; nt < 8; nt++) {
                float bf[2] = { sX[sw64(kb + tg, nt * 8 + g)],
                                sX[sw64(kb + tg + 4, nt * 8 + g)] };
                mma8(accY[nt], a, bf);
            }
        }
    }
    // ---- epilogue: + D*xh, single write ----
    float Dh = Dv[h];
    size_t r0 = (size_t)(rowBase + lbase + w * 16 + g);
#pragma unroll
    for (int nt = 0; nt < 8; nt++) {
        int col = h * HD + nt * 8 + 2 * tg;
        float2 xh0 = *(const float2*)&xbc[r0 * CONVDIM + col];
        float2 xh1 = *(const float2*)&xbc[(r0 + 8) * CONVDIM + col];
        *(float2*)&y[r0 * DIN + col] =
            make_float2(accY[nt][0] + Dh * xh0.x, accY[nt][1] + Dh * xh0.y);
        *(float2*)&y[(r0 + 8) * DIN + col] =
            make_float2(accY[nt][2] + Dh * xh1.x, accY[nt][3] + Dh * xh1.y);
    }
}

// =================== MMA per-chunk states ===================
__global__ __launch_bounds__(128) void states_mma(const float* __restrict__ xbc,
                                                  const float* __restrict__ dtp,
                                                  const float* __restrict__ acum,
                                                  float* __restrict__ states) {
    __shared__ float sX[4096];
    __shared__ float sB[4096];

    int bc = blockIdx.x, h = blockIdx.y;
    int b = bc >> 4, c = bc & 15;
    int rowBase = b * SEQ + c * CHUNK;
    int tid = threadIdx.x, lane = tid & 31, w = tid >> 5;
    int g = lane >> 2, tg = lane & 3;
    int m0 = w * 16;
    const float* acbase = &acum[(bc * NH + h) * CHUNK];
    float aEnd = acbase[CHUNK - 1];

    float acc[8][4];
#pragma unroll
    for (int nt = 0; nt < 8; nt++)
#pragma unroll
        for (int q = 0; q < 4; q++) acc[nt][q] = 0.f;

    for (int st = 0; st < 4; st++) {
        __syncthreads();
        int sbase = st * 64;
        for (int i = tid; i < 64 * 16; i += 128) {
            int r = i >> 4, q = (i & 15) * 4;
            size_t grow = (size_t)(rowBase + sbase + r);
            float dec = __expf(aEnd - acbase[sbase + r]);
            float dtv = dtp[grow * NH + h] * dec;
            float4 xv = *(const float4*)&xbc[grow * CONVDIM + h * HD + q];
            float4 xt = make_float4(tf32r(xv.x * dtv), tf32r(xv.y * dtv),
                                    tf32r(xv.z * dtv), tf32r(xv.w * dtv));
            *(float4*)&sX[r * 64 + ((((q >> 2) ^ (r & 7)) << 2))] = xt;
            float4 bv = *(const float4*)&xbc[grow * CONVDIM + DIN + q];
            float4 bt = make_float4(tf32r(bv.x), tf32r(bv.y), tf32r(bv.z), tf32r(bv.w));
            *(float4*)&sB[r * 64 + ((((q >> 2) ^ (r & 7)) << 2))] = bt;
        }
        __syncthreads();
#pragma unroll
        for (int kb8 = 0; kb8 < 8; kb8++) {
            int kb = kb8 * 8;
            float a[4];
            a[0] = sX[sw64(kb + tg, m0 + g)];
            a[1] = sX[sw64(kb + tg, m0 + g + 8)];
            a[2] = sX[sw64(kb + tg + 4, m0 + g)];
            a[3] = sX[sw64(kb + tg + 4, m0 + g + 8)];
#pragma unroll
            for (int nt = 0; nt < 8; nt++) {
                float bf[2] = { sB[sw64(nt * 8 + g, kb + tg)],
                                sB[sw64(nt * 8 + g, kb + tg + 4)] };
                mma8(acc[nt], a, bf);
            }
        }
    }
    size_t base = (size_t)(bc * NH + h) * (HD * DS);
#pragma unroll
    for (int nt = 0; nt < 8; nt++) {
        int col = nt * 8 + 2 * tg;
        *(float2*)&states[base + (m0 + g) * DS + col]     = make_float2(acc[nt][0], acc[nt][1]);
        *(float2*)&states[base + (m0 + g + 8) * DS + col] = make_float2(acc[nt][2], acc[nt][3]);
    }
}

// ---------------- inter-chunk sequential scan ----------------
__global__ __launch_bounds__(256) void scan_kernel(const float* __restrict__ acum,
                                                   const float* __restrict__ states,
                                                   float* __restrict__ prefix) {
    int b = blockIdx.x, h = blockIdx.y, t = threadIdx.x;
    float S[16];
#pragma unroll
    for (int j = 0; j < 16; j++) S[j] = 0.f;
    for (int c = 0; c < NCH; c++) {
        size_t base = ((size_t)((b * NCH + c) * NH + h)) * (HD * DS) + t * 16;
#pragma unroll
        for (int j = 0; j < 16; j += 4) {
            float4 v = make_float4(S[j], S[j + 1], S[j + 2], S[j + 3]);
            *(float4*)&prefix[base + j] = v;
        }
        float cs = __expf(acum[((b * NCH + c) * NH + h) * CHUNK + (CHUNK - 1)]);
#pragma unroll
        for (int j = 0; j < 16; j += 4) {
            float4 sv = *(const float4*)&states[base + j];
            S[j + 0] = cs * S[j + 0] + sv.x;
            S[j + 1] = cs * S[j + 1] + sv.y;
            S[j + 2] = cs * S[j + 2] + sv.z;
            S[j + 3] = cs * S[j + 3] + sv.w;
        }
    }
}

// ---------------- gate + RMSNorm, emitting bf16 hi/lo directly ----------------
__global__ __launch_bounds__(256) void gate_norm_kernel(const float* __restrict__ zx,
                                                        const float* __restrict__ norm_w,
                                                        const float* __restrict__ y,
                                                        uint2* __restrict__ out_hi,
                                                        uint2* __restrict__ out_lo) {
    int row = blockIdx.x;
    int t = threadIdx.x;
    float4 yv = ((const float4*)&y[(size_t)row * DIN])[t];
    float4 zv = ((const float4*)&zx[(size_t)row * DPROJ])[t];
    float g0 = yv.x * (zv.x / (1.f + __expf(-zv.x)));
    float g1 = yv.y * (zv.y / (1.f + __expf(-zv.y)));
    float g2 = yv.z * (zv.z / (1.f + __expf(-zv.z)));
    float g3 = yv.w * (zv.w / (1.f + __expf(-zv.w)));
    float ss = g0 * g0 + g1 * g1 + g2 * g2 + g3 * g3;
#pragma unroll
    for (int o = 16; o; o >>= 1) ss += __shfl_xor_sync(0xffffffffu, ss, o);
    __shared__ float red[8];
    if ((t & 31) == 0) red[t >> 5] = ss;
    __syncthreads();
    float tot = red[0] + red[1] + red[2] + red[3] + red[4] + red[5] + red[6] + red[7];
    float rms = rsqrtf(tot / (float)DIN + 1e-5f);
    float4 nw = ((const float4*)norm_w)[t];
    float o0 = g0 * rms * nw.x, o1 = g1 * rms * nw.y;
    float o2 = g2 * rms * nw.z, o3 = g3 * rms * nw.w;
    uint32_t h0, l0, h1, l1;
    bsplit2(make_float2(o0, o1), h0, l0);
    bsplit2(make_float2(o2, o3), h1, l1);
    out_hi[(size_t)row * (DIN / 4) + t] = make_uint2(h0, h1);
    out_lo[(size_t)row * (DIN / 4) + t] = make_uint2(l0, l1);
}

// ---------------- launch ----------------
extern "C" void kernel_launch(void* const* d_in, const int* in_sizes, int n_in,
                              void* d_out, int out_size) {
    const float* x_seq      = (const float*)d_in[0];
    const float* in_proj_w  = (const float*)d_in[1];
    const float* conv_w     = (const float*)d_in[2];
    const float* conv_b     = (const float*)d_in[3];
    const float* dt_bias    = (const float*)d_in[4];
    const float* A_log      = (const float*)d_in[5];
    const float* Dv         = (const float*)d_in[6];
    const float* norm_w     = (const float*)d_in[7];
    const float* out_proj_w = (const float*)d_in[8];
    float* out = (float*)d_out;

    float *zx, *xbc, *dtp, *acum, *states, *prefix, *y;
    uint2 *ah, *al, *wh, *wl;
    cudaGetSymbolAddress((void**)&zx, g_zx);
    cudaGetSymbolAddress((void**)&xbc, g_xbc);
    cudaGetSymbolAddress((void**)&dtp, g_dt);
    cudaGetSymbolAddress((void**)&acum, g_acum);
    cudaGetSymbolAddress((void**)&states, g_states);
    cudaGetSymbolAddress((void**)&prefix, g_prefix);
    cudaGetSymbolAddress((void**)&y, g_y);
    cudaGetSymbolAddress((void**)&ah, g_act_hi);
    cudaGetSymbolAddress((void**)&al, g_act_lo);
    cudaGetSymbolAddress((void**)&wh, g_w_hi);
    cudaGetSymbolAddress((void**)&wl, g_w_lo);

    // ---- in_proj ----
    int n4x = NTOK * DMODEL / 4;
    int n4w1 = DPROJ * DMODEL / 4;
    split_kernel<<<592, 512>>>((const float4*)x_seq, ah, al, n4x);
    split_kernel<<<592, 512>>>((const float4*)in_proj_w, wh, wl, n4w1);
    gemm_bf16ld<<<dim3((DPROJ + 63) / 64, NTOK / 64), 128>>>(
        (const uint16_t*)ah, (const uint16_t*)al, (const uint16_t*)wh, (const uint16_t*)wl,
        zx, NTOK, DPROJ, DMODEL);

    conv_kernel<<<(NTOK / 4 * CONVDIM) / 256, 256>>>(zx, conv_w, conv_b, xbc);
    dt_acum_kernel<<<dim3(B_SZ * NCH, NH), CHUNK>>>(zx, dt_bias, A_log, dtp, acum);
    // states + scan BEFORE ydiag (ydiag consumes prefix)
    states_mma<<<dim3(B_SZ * NCH, NH), 128>>>(xbc, dtp, acum, states);
    scan_kernel<<<dim3(B_SZ, NH), 256>>>(acum, states, prefix);
    // fused ydiag + yoff + D*xh
    ydiag_mma<<<dim3(B_SZ * NCH, NH, 4), 128, 49152>>>(xbc, dtp, acum, prefix, Dv, y);
    gate_norm_kernel<<<NTOK, 256>>>(zx, norm_w, y, ah, al);

    // ---- out_proj ----
    int n4w2 = DMODEL * DIN / 4;
    split_kernel<<<592, 512>>>((const float4*)out_proj_w, wh, wl, n4w2);
    gemm_bf16ld<<<dim3(DMODEL / 64, NTOK / 64), 128>>>(
        (const uint16_t*)ah, (const uint16_t*)al, (const uint16_t*)wh, (const uint16_t*)wl,
        out, NTOK, DMODEL, DIN);
}